// round 4
// baseline (speedup 1.0000x reference)
#include <cuda_runtime.h>
#include <math.h>

#define NN 50000
#define NE_MAX 800000
#define TE_MAX (NE_MAX + NN)
#define NG 128

// ---------------- scratch (device globals; no allocation) ----------------
__device__ __align__(16) float d_h1[NN * 256];    // x@W1 (4 heads x 64ch)
__device__ __align__(16) float d_g1[NN * 256];    // elu(gat1 + b1)
__device__ __align__(16) float d_ss1[NN * 4];
__device__ __align__(16) float d_sd1[NN * 4];
__device__ __align__(16) float d_h2[NN * 64];     // g1@W2
__device__ __align__(16) float d_xg[NN * 64];     // x@Wg
__device__ float d_ss2[NN];
__device__ float d_sd2[NN];
__device__ float d_dinv[NN];
__device__ float d_pooled[NG * 64];
__device__ float d_gcnt[NG];
// CSR by destination
__device__ int d_cnt_i[NN];
__device__ int d_cur[NN];
__device__ int d_off[NN + 1];
__device__ int d_csr[TE_MAX];

__device__ __forceinline__ float lrelu(float u) { return u > 0.f ? u : 0.2f * u; }
__device__ __forceinline__ float elu(float u)   { return u > 0.f ? u : expm1f(u); }

// ---------------- init: zero counters / accumulators ----------------
__global__ void k_init() {
    int i  = blockIdx.x * blockDim.x + threadIdx.x;
    int st = gridDim.x * blockDim.x;
    for (int j = i; j < NN; j += st) d_cnt_i[j] = 0;
    for (int j = i; j < NG * 64; j += st) d_pooled[j] = 0.f;
    for (int j = i; j < NG; j += st) d_gcnt[j] = 0.f;
}

// ---------------- node pass 1: h1 = x@W1, ss1/sd1, xg = x@Wg ----------------
__global__ void k_h1(const float* __restrict__ x, const float* __restrict__ W1,
                     const float* __restrict__ as1, const float* __restrict__ ad1,
                     const float* __restrict__ Wg) {
    int n = blockIdx.x, t = threadIdx.x;
    __shared__ float sx[14];
    __shared__ float sred[16];
    if (t < 14) sx[t] = x[n * 14 + t];
    __syncthreads();
    float acc = 0.f;
#pragma unroll
    for (int k = 0; k < 14; k++) acc += sx[k] * W1[k * 256 + t];
    d_h1[n * 256 + t] = acc;

    if (t < 64) {
        float xa = 0.f;
#pragma unroll
        for (int k = 0; k < 14; k++) xa += sx[k] * Wg[k * 64 + t];
        d_xg[n * 64 + t] = xa;
    }

    float ps = acc * as1[t], pd = acc * ad1[t];
#pragma unroll
    for (int o = 16; o > 0; o >>= 1) {
        ps += __shfl_down_sync(0xFFFFFFFFu, ps, o);
        pd += __shfl_down_sync(0xFFFFFFFFu, pd, o);
    }
    int w = t >> 5;
    if ((t & 31) == 0) { sred[w] = ps; sred[8 + w] = pd; }
    __syncthreads();
    if ((t & 63) == 0) {
        int h = t >> 6;
        d_ss1[n * 4 + h] = sred[2 * h] + sred[2 * h + 1];
        d_sd1[n * 4 + h] = sred[8 + 2 * h] + sred[8 + 2 * h + 1];
    }
}

// ---------------- CSR build: count, scan, fill ----------------
__global__ void k_count(const int* __restrict__ ei, int E, int te) {
    int e = blockIdx.x * blockDim.x + threadIdx.x;
    if (e >= te) return;
    int d = (e < E) ? ei[E + e] : (e - E);
    atomicAdd(&d_cnt_i[d], 1);
}

__global__ void k_scan() {  // single block, 1024 threads
    const int CH = (NN + 1023) / 1024;  // 49
    __shared__ int ssum[1024];
    int t = threadIdx.x;
    int base = t * CH;
    int s = 0;
    for (int j = 0; j < CH; j++) {
        int idx = base + j;
        if (idx < NN) s += d_cnt_i[idx];
    }
    ssum[t] = s;
    __syncthreads();
    // Hillis-Steele inclusive scan
    for (int o = 1; o < 1024; o <<= 1) {
        int v = (t >= o) ? ssum[t - o] : 0;
        __syncthreads();
        ssum[t] += v;
        __syncthreads();
    }
    int run = (t > 0) ? ssum[t - 1] : 0;
    for (int j = 0; j < CH; j++) {
        int idx = base + j;
        if (idx < NN) {
            d_off[idx] = run;
            d_cur[idx] = run;
            run += d_cnt_i[idx];
        }
    }
    if (t == 1023) d_off[NN] = ssum[1023];
}

__global__ void k_fill(const int* __restrict__ ei, int E, int te) {
    int e = blockIdx.x * blockDim.x + threadIdx.x;
    if (e >= te) return;
    int s, d;
    if (e < E) { s = ei[e]; d = ei[E + e]; } else { s = d = e - E; }
    int pos = atomicAdd(&d_cur[d], 1);
    d_csr[pos] = s;
}

// ---------------- GAT1 gather: warp per dst node, fused softmax+aggregate+bias+ELU ----------------
__global__ void k_gat1(const float* __restrict__ b1) {
    int t = threadIdx.x, lane = t & 31, w = t >> 5;
    int n = blockIdx.x * 8 + w;
    if (n >= NN) return;
    int head = lane >> 3;
    float sdv = d_sd1[n * 4 + head];
    int beg = d_off[n], end = d_off[n + 1];
    float a0 = 0.f, a1 = 0.f, a2 = 0.f, a3 = 0.f, a4 = 0.f, a5 = 0.f, a6 = 0.f, a7 = 0.f;
    float den = 0.f;
    for (int i = beg; i < end; i++) {
        int s = d_csr[i];
        float e = __expf(lrelu(d_ss1[s * 4 + head] + sdv));
        den += e;
        const float4* hp = (const float4*)(d_h1 + (long)s * 256);
        float4 p0 = hp[lane * 2], p1 = hp[lane * 2 + 1];
        a0 += p0.x * e; a1 += p0.y * e; a2 += p0.z * e; a3 += p0.w * e;
        a4 += p1.x * e; a5 += p1.y * e; a6 += p1.z * e; a7 += p1.w * e;
    }
    float inv = 1.f / (den + 1e-16f);
    int c0 = lane * 8;
    float4 o0, o1;
    o0.x = elu(a0 * inv + b1[c0 + 0]);
    o0.y = elu(a1 * inv + b1[c0 + 1]);
    o0.z = elu(a2 * inv + b1[c0 + 2]);
    o0.w = elu(a3 * inv + b1[c0 + 3]);
    o1.x = elu(a4 * inv + b1[c0 + 4]);
    o1.y = elu(a5 * inv + b1[c0 + 5]);
    o1.z = elu(a6 * inv + b1[c0 + 6]);
    o1.w = elu(a7 * inv + b1[c0 + 7]);
    float4* op = (float4*)(d_g1 + (long)n * 256);
    op[lane * 2] = o0;
    op[lane * 2 + 1] = o1;
}

// ---------------- node pass 2: h2 = g1@W2; ss2/sd2; dinv ----------------
__global__ void k_node2(const float* __restrict__ W2,
                        const float* __restrict__ as2, const float* __restrict__ ad2) {
    int n = blockIdx.x, t = threadIdx.x;
    __shared__ float sg[256];
    __shared__ float sp[256];
    __shared__ float r2[4];
    sg[t] = d_g1[n * 256 + t];
    __syncthreads();
    int out = t & 63, part = t >> 6;
    float acc = 0.f;
    int k0 = part * 64;
#pragma unroll 8
    for (int k = 0; k < 64; k++) acc += sg[k0 + k] * W2[(k0 + k) * 64 + out];
    sp[t] = acc;
    __syncthreads();
    if (t < 64) {
        float h2 = sp[t] + sp[64 + t] + sp[128 + t] + sp[192 + t];
        d_h2[n * 64 + t] = h2;
        float ps = h2 * as2[t], pd = h2 * ad2[t];
#pragma unroll
        for (int o = 16; o > 0; o >>= 1) {
            ps += __shfl_down_sync(0xFFFFFFFFu, ps, o);
            pd += __shfl_down_sync(0xFFFFFFFFu, pd, o);
        }
        if ((t & 31) == 0) { r2[t >> 5] = ps; r2[2 + (t >> 5)] = pd; }
    }
    __syncthreads();
    if (t == 0) {
        d_ss2[n] = r2[0] + r2[1];
        d_sd2[n] = r2[2] + r2[3];
        d_dinv[n] = rsqrtf((float)d_cnt_i[n]);
    }
}

// ---------------- GAT2 + GCN gather + fuse + pool: warp per dst node ----------------
__global__ void k_gat2(const float* __restrict__ b2, const float* __restrict__ bg,
                       const float* __restrict__ Wf, const float* __restrict__ bf,
                       const int* __restrict__ batch) {
    int t = threadIdx.x, lane = t & 31, w = t >> 5;
    int n = blockIdx.x * 8 + w;
    __shared__ float sf[8][128];
    bool valid = n < NN;
    if (valid) {
        float sdv = d_sd2[n];
        float dv = d_dinv[n];
        int beg = d_off[n], end = d_off[n + 1];
        float a0 = 0.f, a1 = 0.f, g0 = 0.f, g1 = 0.f, den = 0.f;
        for (int i = beg; i < end; i++) {
            int s = d_csr[i];
            float e = __expf(lrelu(d_ss2[s] + sdv));
            den += e;
            float2 h = ((const float2*)(d_h2 + (long)s * 64))[lane];
            a0 += h.x * e; a1 += h.y * e;
            float nm = d_dinv[s] * dv;
            float2 xv = ((const float2*)(d_xg + (long)s * 64))[lane];
            g0 += xv.x * nm; g1 += xv.y * nm;
        }
        float inv = 1.f / (den + 1e-16f);
        int c = 2 * lane;
        sf[w][c]       = elu(a0 * inv + b2[c]);
        sf[w][c + 1]   = elu(a1 * inv + b2[c + 1]);
        sf[w][64 + c]     = fmaxf(g0 + bg[c], 0.f);
        sf[w][64 + c + 1] = fmaxf(g1 + bg[c + 1], 0.f);
    }
    __syncthreads();
    if (valid) {
        int c = 2 * lane;
        float acc0 = bf[c], acc1 = bf[c + 1];
        const float* sp = sf[w];
#pragma unroll 8
        for (int k = 0; k < 128; k++) {
            float v = sp[k];
            acc0 += v * Wf[k * 64 + c];
            acc1 += v * Wf[k * 64 + c + 1];
        }
        acc0 = fmaxf(acc0, 0.f);
        acc1 = fmaxf(acc1, 0.f);
        int b = batch[n];
        atomicAdd(d_pooled + b * 64 + c, acc0);
        atomicAdd(d_pooled + b * 64 + c + 1, acc1);
        if (lane == 0) atomicAdd(d_gcnt + b, 1.0f);
    }
}

// ---------------- heads: pooled mean -> 2x (relu MLP 64->32->5) ----------------
__global__ void k_head(const float* __restrict__ Wc1, const float* __restrict__ bc1,
                       const float* __restrict__ Wc2, const float* __restrict__ bc2,
                       const float* __restrict__ Wp1, const float* __restrict__ bp1,
                       const float* __restrict__ Wp2, const float* __restrict__ bp2,
                       float* __restrict__ out) {
    int g = blockIdx.x, t = threadIdx.x;
    __shared__ float sp[64], sh[64];
    float cnt = fmaxf(d_gcnt[g], 1.0f);
    sp[t] = d_pooled[g * 64 + t] / cnt;
    __syncthreads();
    float hv;
    if (t < 32) {
        hv = bc1[t];
#pragma unroll 8
        for (int k = 0; k < 64; k++) hv += sp[k] * Wc1[k * 32 + t];
    } else {
        int j = t - 32;
        hv = bp1[j];
#pragma unroll 8
        for (int k = 0; k < 64; k++) hv += sp[k] * Wp1[k * 32 + j];
    }
    sh[t] = fmaxf(hv, 0.f);
    __syncthreads();
    if (t < 5) {
        float o = bc2[t];
#pragma unroll
        for (int j = 0; j < 32; j++) o += sh[j] * Wc2[j * 5 + t];
        out[g * 5 + t] = o;
    } else if (t >= 8 && t < 13) {
        int u = t - 8;
        float o = bp2[u];
#pragma unroll
        for (int j = 0; j < 32; j++) o += sh[32 + j] * Wp2[j * 5 + u];
        out[NG * 5 + g * 5 + u] = o;
    }
}

extern "C" void kernel_launch(void* const* d_in, const int* in_sizes, int n_in,
                              void* d_out, int out_size) {
    const float* x     = (const float*)d_in[0];
    const int*   ei    = (const int*)d_in[1];     // int32 (JAX x64 disabled)
    const int*   batch = (const int*)d_in[3];     // int32
    const float* W1  = (const float*)d_in[4];
    const float* as1 = (const float*)d_in[5];
    const float* ad1 = (const float*)d_in[6];
    const float* b1  = (const float*)d_in[7];
    const float* W2  = (const float*)d_in[8];
    const float* as2 = (const float*)d_in[9];
    const float* ad2 = (const float*)d_in[10];
    const float* b2  = (const float*)d_in[11];
    const float* Wg  = (const float*)d_in[12];
    const float* bg  = (const float*)d_in[13];
    const float* Wf  = (const float*)d_in[14];
    const float* bf  = (const float*)d_in[15];
    const float* Wc1 = (const float*)d_in[16];
    const float* bc1 = (const float*)d_in[17];
    const float* Wc2 = (const float*)d_in[18];
    const float* bc2 = (const float*)d_in[19];
    const float* Wp1 = (const float*)d_in[20];
    const float* bp1 = (const float*)d_in[21];
    const float* Wp2 = (const float*)d_in[22];
    const float* bp2 = (const float*)d_in[23];

    int E  = in_sizes[1] / 2;
    int te = E + NN;
    int eb = (te + 255) / 256;

    k_init<<<512, 256>>>();
    k_h1<<<NN, 256>>>(x, W1, as1, ad1, Wg);
    k_count<<<eb, 256>>>(ei, E, te);
    k_scan<<<1, 1024>>>();
    k_fill<<<eb, 256>>>(ei, E, te);
    k_gat1<<<(NN + 7) / 8, 256>>>(b1);
    k_node2<<<NN, 256>>>(W2, as2, ad2);
    k_gat2<<<(NN + 7) / 8, 256>>>(b2, bg, Wf, bf, batch);
    k_head<<<NG, 64>>>(Wc1, bc1, Wc2, bc2, Wp1, bp1, Wp2, bp2, (float*)d_out);
}

// round 5
// speedup vs baseline: 1.3103x; 1.3103x over previous
#include <cuda_runtime.h>
#include <math.h>

#define NN 50000
#define NE_MAX 800000
#define TE_MAX (NE_MAX + NN)
#define NG 128
#define SB 49   // scan blocks (49*1024 >= 50000)

// ---------------- scratch (device globals; no allocation) ----------------
__device__ __align__(16) float d_h1[NN * 256];    // x@W1 (4 heads x 64ch)
__device__ __align__(16) float d_g1[NN * 256];    // elu(gat1 + b1)
__device__ __align__(16) float d_ss1[NN * 4];
__device__ __align__(16) float d_sd1[NN * 4];
__device__ __align__(16) float d_h2[NN * 64];     // g1@W2
__device__ __align__(16) float d_xg[NN * 64];     // x@Wg
__device__ float d_ss2[NN];
__device__ float d_sd2[NN];
__device__ float d_dinv[NN];
__device__ float d_pooled[NG * 64];
__device__ float d_gcnt[NG];
// CSR by destination
__device__ int d_cnt_i[NN];
__device__ int d_cur[NN];
__device__ int d_off[NN + 1];
__device__ int d_csr[TE_MAX];
__device__ int d_bsum[64];

__device__ __forceinline__ float lrelu(float u) { return u > 0.f ? u : 0.2f * u; }
__device__ __forceinline__ float elu(float u)   { return u > 0.f ? u : expm1f(u); }

// ---------------- init: zero counters / accumulators ----------------
__global__ void k_init() {
    int i  = blockIdx.x * blockDim.x + threadIdx.x;
    int st = gridDim.x * blockDim.x;
    for (int j = i; j < NN; j += st) d_cnt_i[j] = 0;
    for (int j = i; j < NG * 64; j += st) d_pooled[j] = 0.f;
    for (int j = i; j < NG; j += st) d_gcnt[j] = 0.f;
}

// ---------------- node pass 1: 16 nodes/block, weights staged in smem ----------------
#define H1N 16
__global__ void k_h1(const float* __restrict__ x, const float* __restrict__ W1,
                     const float* __restrict__ as1, const float* __restrict__ ad1,
                     const float* __restrict__ Wg) {
    __shared__ float sW1[14 * 256];
    __shared__ float sWg[14 * 64];
    __shared__ float sas[256], sad[256];
    __shared__ float sx[H1N][14];
    __shared__ float sredp[8], sredd[8];
    int t = threadIdx.x;
    int nb = blockIdx.x * H1N;
    for (int i = t; i < 14 * 256; i += 256) sW1[i] = W1[i];
    for (int i = t; i < 14 * 64; i += 256) sWg[i] = Wg[i];
    sas[t] = as1[t];
    sad[t] = ad1[t];
    if (t < H1N * 14) {
        int nn = t / 14, k = t % 14;
        int n = nb + nn;
        sx[nn][k] = (n < NN) ? x[n * 14 + k] : 0.f;
    }
    __syncthreads();
    int lane = t & 31, w = t >> 5;
#pragma unroll 1
    for (int i = 0; i < H1N; i++) {
        int n = nb + i;
        if (n < NN) {
            float acc = 0.f;
#pragma unroll
            for (int k = 0; k < 14; k++) acc += sx[i][k] * sW1[k * 256 + t];
            d_h1[(long)n * 256 + t] = acc;
            if (t < 64) {
                float xa = 0.f;
#pragma unroll
                for (int k = 0; k < 14; k++) xa += sx[i][k] * sWg[k * 64 + t];
                d_xg[n * 64 + t] = xa;
            }
            float ps = acc * sas[t], pd = acc * sad[t];
#pragma unroll
            for (int o = 16; o > 0; o >>= 1) {
                ps += __shfl_down_sync(0xFFFFFFFFu, ps, o);
                pd += __shfl_down_sync(0xFFFFFFFFu, pd, o);
            }
            if (lane == 0) { sredp[w] = ps; sredd[w] = pd; }
        }
        __syncthreads();
        if (n < NN && t < 4) {
            d_ss1[n * 4 + t] = sredp[2 * t] + sredp[2 * t + 1];
            d_sd1[n * 4 + t] = sredd[2 * t] + sredd[2 * t + 1];
        }
        __syncthreads();
    }
}

// ---------------- CSR build: count, 3-phase scan, fill ----------------
__global__ void k_count(const int* __restrict__ ei, int E, int te) {
    int e = blockIdx.x * blockDim.x + threadIdx.x;
    if (e >= te) return;
    int d = (e < E) ? ei[E + e] : (e - E);
    atomicAdd(&d_cnt_i[d], 1);
}

__global__ void k_scan1() {  // grid SB, 1024 thr: per-block exclusive scan + block sums
    __shared__ int sh[1024];
    int t = threadIdx.x;
    int idx = blockIdx.x * 1024 + t;
    int v = (idx < NN) ? d_cnt_i[idx] : 0;
    sh[t] = v;
    __syncthreads();
    for (int o = 1; o < 1024; o <<= 1) {
        int u = (t >= o) ? sh[t - o] : 0;
        __syncthreads();
        sh[t] += u;
        __syncthreads();
    }
    if (idx < NN) d_off[idx] = sh[t] - v;   // exclusive within block
    if (t == 1023) d_bsum[blockIdx.x] = sh[1023];
}

__global__ void k_scan2() {  // 1 block, 64 thr: exclusive scan of block sums
    __shared__ int sh[64];
    int t = threadIdx.x;
    int v = (t < SB) ? d_bsum[t] : 0;
    sh[t] = v;
    __syncthreads();
    for (int o = 1; o < 64; o <<= 1) {
        int u = (t >= o) ? sh[t - o] : 0;
        __syncthreads();
        sh[t] += u;
        __syncthreads();
    }
    if (t < SB) d_bsum[t] = sh[t] - v;
    if (t == 63) d_off[NN] = sh[63];
}

__global__ void k_scan3() {  // apply block prefix
    int idx = blockIdx.x * blockDim.x + threadIdx.x;
    if (idx >= NN) return;
    int o = d_off[idx] + d_bsum[idx >> 10];
    d_off[idx] = o;
    d_cur[idx] = o;
}

__global__ void k_fill(const int* __restrict__ ei, int E, int te) {
    int e = blockIdx.x * blockDim.x + threadIdx.x;
    if (e >= te) return;
    int s, d;
    if (e < E) { s = ei[e]; d = ei[E + e]; } else { s = d = e - E; }
    int pos = atomicAdd(&d_cur[d], 1);
    d_csr[pos] = s;
}

// ---------------- GAT1 gather: warp per dst node, fused softmax+aggregate+bias+ELU ----------------
__global__ void k_gat1(const float* __restrict__ b1) {
    int t = threadIdx.x, lane = t & 31, w = t >> 5;
    int n = blockIdx.x * 8 + w;
    if (n >= NN) return;
    int head = lane >> 3;
    float sdv = d_sd1[n * 4 + head];
    int beg = d_off[n], end = d_off[n + 1];
    float a0 = 0.f, a1 = 0.f, a2 = 0.f, a3 = 0.f, a4 = 0.f, a5 = 0.f, a6 = 0.f, a7 = 0.f;
    float den = 0.f;
    for (int i = beg; i < end; i++) {
        int s = d_csr[i];
        float e = __expf(lrelu(d_ss1[s * 4 + head] + sdv));
        den += e;
        const float4* hp = (const float4*)(d_h1 + (long)s * 256);
        float4 p0 = hp[lane * 2], p1 = hp[lane * 2 + 1];
        a0 += p0.x * e; a1 += p0.y * e; a2 += p0.z * e; a3 += p0.w * e;
        a4 += p1.x * e; a5 += p1.y * e; a6 += p1.z * e; a7 += p1.w * e;
    }
    float inv = 1.f / (den + 1e-16f);
    int c0 = lane * 8;
    float4 o0, o1;
    o0.x = elu(a0 * inv + b1[c0 + 0]);
    o0.y = elu(a1 * inv + b1[c0 + 1]);
    o0.z = elu(a2 * inv + b1[c0 + 2]);
    o0.w = elu(a3 * inv + b1[c0 + 3]);
    o1.x = elu(a4 * inv + b1[c0 + 4]);
    o1.y = elu(a5 * inv + b1[c0 + 5]);
    o1.z = elu(a6 * inv + b1[c0 + 6]);
    o1.w = elu(a7 * inv + b1[c0 + 7]);
    float4* op = (float4*)(d_g1 + (long)n * 256);
    op[lane * 2] = o0;
    op[lane * 2 + 1] = o1;
}

// ---------------- node pass 2: tiled GEMM h2 = g1 @ W2 (64 nodes x 64 out per block) ----------------
__global__ void k_node2(const float* __restrict__ W2) {
    __shared__ float sA[64][68];
    __shared__ float sB[64][68];
    int t = threadIdx.x;
    int nb = blockIdx.x * 64;
    int tn = t >> 4, tc = t & 15;
    float acc[4][4] = {};
#pragma unroll 1
    for (int kc = 0; kc < 4; kc++) {
#pragma unroll
        for (int j = 0; j < 4; j++) {
            int f4 = t * 4 + j;            // 0..1023
            int row = f4 >> 4;             // 0..63
            int col4 = f4 & 15;            // float4 slot
            int n = nb + row;
            float4 v = (n < NN) ? ((const float4*)(d_g1 + (long)n * 256 + kc * 64))[col4]
                                : make_float4(0.f, 0.f, 0.f, 0.f);
            ((float4*)&sA[row][0])[col4] = v;
            float4 wv = ((const float4*)(W2 + (kc * 64 + row) * 64))[col4];
            ((float4*)&sB[row][0])[col4] = wv;
        }
        __syncthreads();
#pragma unroll 4
        for (int kk = 0; kk < 64; kk++) {
            float4 bv = ((float4*)&sB[kk][0])[tc];
#pragma unroll
            for (int i = 0; i < 4; i++) {
                float av = sA[tn * 4 + i][kk];
                acc[i][0] += av * bv.x; acc[i][1] += av * bv.y;
                acc[i][2] += av * bv.z; acc[i][3] += av * bv.w;
            }
        }
        __syncthreads();
    }
#pragma unroll
    for (int i = 0; i < 4; i++) {
        int n = nb + tn * 4 + i;
        if (n < NN)
            ((float4*)(d_h2 + (long)n * 64))[tc] =
                make_float4(acc[i][0], acc[i][1], acc[i][2], acc[i][3]);
    }
}

// ---------------- attention scores layer 2 + dinv: warp per node ----------------
__global__ void k_att2(const float* __restrict__ as2, const float* __restrict__ ad2) {
    int t = threadIdx.x, lane = t & 31, w = t >> 5;
    int n = blockIdx.x * 8 + w;
    if (n >= NN) return;
    float2 h = ((const float2*)(d_h2 + (long)n * 64))[lane];
    float2 a = ((const float2*)as2)[lane];
    float2 d = ((const float2*)ad2)[lane];
    float ps = h.x * a.x + h.y * a.y;
    float pd = h.x * d.x + h.y * d.y;
#pragma unroll
    for (int o = 16; o > 0; o >>= 1) {
        ps += __shfl_down_sync(0xFFFFFFFFu, ps, o);
        pd += __shfl_down_sync(0xFFFFFFFFu, pd, o);
    }
    if (lane == 0) {
        d_ss2[n] = ps;
        d_sd2[n] = pd;
        d_dinv[n] = rsqrtf((float)d_cnt_i[n]);
    }
}

// ---------------- GAT2 + GCN gather + fuse + pool: warp per dst node, Wf in smem ----------------
__global__ void k_gat2(const float* __restrict__ b2, const float* __restrict__ bg,
                       const float* __restrict__ Wf, const float* __restrict__ bf,
                       const int* __restrict__ batch) {
    __shared__ float sWf[128 * 64];
    __shared__ float sf[8][128];
    __shared__ float sb2[64], sbg[64], sbf[64];
    int t = threadIdx.x, lane = t & 31, w = t >> 5;
    int n = blockIdx.x * 8 + w;
    for (int i = t; i < 128 * 64 / 4; i += 256) ((float4*)sWf)[i] = ((const float4*)Wf)[i];
    if (t < 64) { sb2[t] = b2[t]; sbg[t] = bg[t]; sbf[t] = bf[t]; }
    __syncthreads();
    bool valid = n < NN;
    if (valid) {
        float sdv = d_sd2[n];
        float dv = d_dinv[n];
        int beg = d_off[n], end = d_off[n + 1];
        float a0 = 0.f, a1 = 0.f, g0 = 0.f, g1 = 0.f, den = 0.f;
        for (int i = beg; i < end; i++) {
            int s = d_csr[i];
            float e = __expf(lrelu(d_ss2[s] + sdv));
            den += e;
            float2 h = ((const float2*)(d_h2 + (long)s * 64))[lane];
            a0 += h.x * e; a1 += h.y * e;
            float nm = d_dinv[s] * dv;
            float2 xv = ((const float2*)(d_xg + (long)s * 64))[lane];
            g0 += xv.x * nm; g1 += xv.y * nm;
        }
        float inv = 1.f / (den + 1e-16f);
        int c = 2 * lane;
        sf[w][c]          = elu(a0 * inv + sb2[c]);
        sf[w][c + 1]      = elu(a1 * inv + sb2[c + 1]);
        sf[w][64 + c]     = fmaxf(g0 + sbg[c], 0.f);
        sf[w][64 + c + 1] = fmaxf(g1 + sbg[c + 1], 0.f);
    }
    __syncthreads();
    if (valid) {
        int c = 2 * lane;
        float acc0 = sbf[c], acc1 = sbf[c + 1];
        const float* sp = sf[w];
#pragma unroll 8
        for (int k = 0; k < 128; k++) {
            float v = sp[k];
            float2 wv = ((const float2*)&sWf[k * 64])[lane];
            acc0 += v * wv.x;
            acc1 += v * wv.y;
        }
        acc0 = fmaxf(acc0, 0.f);
        acc1 = fmaxf(acc1, 0.f);
        int b = batch[n];
        atomicAdd(d_pooled + b * 64 + c, acc0);
        atomicAdd(d_pooled + b * 64 + c + 1, acc1);
        if (lane == 0) atomicAdd(d_gcnt + b, 1.0f);
    }
}

// ---------------- heads: pooled mean -> 2x (relu MLP 64->32->5) ----------------
__global__ void k_head(const float* __restrict__ Wc1, const float* __restrict__ bc1,
                       const float* __restrict__ Wc2, const float* __restrict__ bc2,
                       const float* __restrict__ Wp1, const float* __restrict__ bp1,
                       const float* __restrict__ Wp2, const float* __restrict__ bp2,
                       float* __restrict__ out) {
    int g = blockIdx.x, t = threadIdx.x;
    __shared__ float sp[64], sh[64];
    float cnt = fmaxf(d_gcnt[g], 1.0f);
    sp[t] = d_pooled[g * 64 + t] / cnt;
    __syncthreads();
    float hv;
    if (t < 32) {
        hv = bc1[t];
#pragma unroll 8
        for (int k = 0; k < 64; k++) hv += sp[k] * Wc1[k * 32 + t];
    } else {
        int j = t - 32;
        hv = bp1[j];
#pragma unroll 8
        for (int k = 0; k < 64; k++) hv += sp[k] * Wp1[k * 32 + j];
    }
    sh[t] = fmaxf(hv, 0.f);
    __syncthreads();
    if (t < 5) {
        float o = bc2[t];
#pragma unroll
        for (int j = 0; j < 32; j++) o += sh[j] * Wc2[j * 5 + t];
        out[g * 5 + t] = o;
    } else if (t >= 8 && t < 13) {
        int u = t - 8;
        float o = bp2[u];
#pragma unroll
        for (int j = 0; j < 32; j++) o += sh[32 + j] * Wp2[j * 5 + u];
        out[NG * 5 + g * 5 + u] = o;
    }
}

extern "C" void kernel_launch(void* const* d_in, const int* in_sizes, int n_in,
                              void* d_out, int out_size) {
    const float* x     = (const float*)d_in[0];
    const int*   ei    = (const int*)d_in[1];     // int32 (JAX x64 disabled)
    const int*   batch = (const int*)d_in[3];     // int32
    const float* W1  = (const float*)d_in[4];
    const float* as1 = (const float*)d_in[5];
    const float* ad1 = (const float*)d_in[6];
    const float* b1  = (const float*)d_in[7];
    const float* W2  = (const float*)d_in[8];
    const float* as2 = (const float*)d_in[9];
    const float* ad2 = (const float*)d_in[10];
    const float* b2  = (const float*)d_in[11];
    const float* Wg  = (const float*)d_in[12];
    const float* bg  = (const float*)d_in[13];
    const float* Wf  = (const float*)d_in[14];
    const float* bf  = (const float*)d_in[15];
    const float* Wc1 = (const float*)d_in[16];
    const float* bc1 = (const float*)d_in[17];
    const float* Wc2 = (const float*)d_in[18];
    const float* bc2 = (const float*)d_in[19];
    const float* Wp1 = (const float*)d_in[20];
    const float* bp1 = (const float*)d_in[21];
    const float* Wp2 = (const float*)d_in[22];
    const float* bp2 = (const float*)d_in[23];

    int E  = in_sizes[1] / 2;
    int te = E + NN;
    int eb = (te + 255) / 256;

    k_init<<<512, 256>>>();
    k_h1<<<(NN + H1N - 1) / H1N, 256>>>(x, W1, as1, ad1, Wg);
    k_count<<<eb, 256>>>(ei, E, te);
    k_scan1<<<SB, 1024>>>();
    k_scan2<<<1, 64>>>();
    k_scan3<<<(NN + 255) / 256, 256>>>();
    k_fill<<<eb, 256>>>(ei, E, te);
    k_gat1<<<(NN + 7) / 8, 256>>>(b1);
    k_node2<<<(NN + 63) / 64, 256>>>(W2);
    k_att2<<<(NN + 7) / 8, 256>>>(as2, ad2);
    k_gat2<<<(NN + 7) / 8, 256>>>(b2, bg, Wf, bf, batch);
    k_head<<<NG, 64>>>(Wc1, bc1, Wc2, bc2, Wp1, bp1, Wp2, bp2, (float*)d_out);
}

// round 6
// speedup vs baseline: 1.4197x; 1.0835x over previous
#include <cuda_runtime.h>
#include <math.h>

#define NN 50000
#define NE_MAX 800000
#define TE_MAX (NE_MAX + NN)
#define NG 128
#define SB 49   // scan blocks (49*1024 >= 50000)

// ---------------- scratch (device globals; no allocation) ----------------
__device__ __align__(16) float d_h1[NN * 256];    // x@W1 (4 heads x 64ch)
__device__ __align__(16) float d_g1[NN * 256];    // elu(gat1 + b1)
__device__ __align__(16) float d_ss1[NN * 4];
__device__ __align__(16) float d_sd1[NN * 4];
__device__ __align__(16) float d_h2[NN * 64];     // g1@W2
__device__ __align__(16) float d_xg[NN * 64];     // x@Wg
__device__ float d_ss2[NN];
__device__ float d_sd2[NN];
__device__ float d_dinv[NN];
__device__ float d_pooled[NG * 64];
__device__ float d_gcnt[NG];
// CSR by destination
__device__ int d_cnt_i[NN];
__device__ int d_off[NN + 1];
__device__ int d_csr[TE_MAX];
__device__ int d_bsum[64];

__device__ __forceinline__ float lrelu(float u) { return u > 0.f ? u : 0.2f * u; }
__device__ __forceinline__ float elu(float u)   { return u > 0.f ? u : expm1f(u); }

// ---------------- init: zero counters / accumulators ----------------
__global__ void k_init() {
    int i  = blockIdx.x * blockDim.x + threadIdx.x;
    int st = gridDim.x * blockDim.x;
    for (int j = i; j < NN; j += st) d_cnt_i[j] = 0;
    for (int j = i; j < NG * 64; j += st) d_pooled[j] = 0.f;
    for (int j = i; j < NG; j += st) d_gcnt[j] = 0.f;
}

// ---------------- CSR count ----------------
__global__ void k_count(const int* __restrict__ ei, int E, int te) {
    int e = blockIdx.x * blockDim.x + threadIdx.x;
    if (e >= te) return;
    int d = (e < E) ? ei[E + e] : (e - E);
    atomicAdd(&d_cnt_i[d], 1);
}

__global__ void k_scan1() {  // grid SB, 1024 thr: per-block exclusive scan + block sums
    __shared__ int sh[1024];
    int t = threadIdx.x;
    int idx = blockIdx.x * 1024 + t;
    int v = (idx < NN) ? d_cnt_i[idx] : 0;
    sh[t] = v;
    __syncthreads();
    for (int o = 1; o < 1024; o <<= 1) {
        int u = (t >= o) ? sh[t - o] : 0;
        __syncthreads();
        sh[t] += u;
        __syncthreads();
    }
    if (idx < NN) d_off[idx] = sh[t] - v;   // exclusive within block
    if (t == 1023) d_bsum[blockIdx.x] = sh[1023];
}

// ---------------- node pass 1: 16 nodes/block, weights staged in smem ----------------
#define H1N 16
__global__ void k_h1(const float* __restrict__ x, const float* __restrict__ W1,
                     const float* __restrict__ as1, const float* __restrict__ ad1,
                     const float* __restrict__ Wg) {
    __shared__ float sW1[14 * 256];
    __shared__ float sWg[14 * 64];
    __shared__ float sas[256], sad[256];
    __shared__ float sx[H1N][14];
    __shared__ float sredp[8], sredd[8];
    int t = threadIdx.x;
    int nb = blockIdx.x * H1N;
    for (int i = t; i < 14 * 256; i += 256) sW1[i] = W1[i];
    for (int i = t; i < 14 * 64; i += 256) sWg[i] = Wg[i];
    sas[t] = as1[t];
    sad[t] = ad1[t];
    if (t < H1N * 14) {
        int nn = t / 14, k = t % 14;
        int n = nb + nn;
        sx[nn][k] = (n < NN) ? x[n * 14 + k] : 0.f;
    }
    __syncthreads();
    int lane = t & 31, w = t >> 5;
#pragma unroll 1
    for (int i = 0; i < H1N; i++) {
        int n = nb + i;
        if (n < NN) {
            float acc = 0.f;
#pragma unroll
            for (int k = 0; k < 14; k++) acc += sx[i][k] * sW1[k * 256 + t];
            d_h1[(long)n * 256 + t] = acc;
            if (t < 64) {
                float xa = 0.f;
#pragma unroll
                for (int k = 0; k < 14; k++) xa += sx[i][k] * sWg[k * 64 + t];
                d_xg[n * 64 + t] = xa;
            }
            float ps = acc * sas[t], pd = acc * sad[t];
#pragma unroll
            for (int o = 16; o > 0; o >>= 1) {
                ps += __shfl_down_sync(0xFFFFFFFFu, ps, o);
                pd += __shfl_down_sync(0xFFFFFFFFu, pd, o);
            }
            if (lane == 0) { sredp[w] = ps; sredd[w] = pd; }
        }
        __syncthreads();
        if (n < NN && t < 4) {
            d_ss1[n * 4 + t] = sredp[2 * t] + sredp[2 * t + 1];
            d_sd1[n * 4 + t] = sredd[2 * t] + sredd[2 * t + 1];
        }
        __syncthreads();
    }
}

__global__ void k_scan2() {  // 1 block, 64 thr: exclusive scan of block sums
    __shared__ int sh[64];
    int t = threadIdx.x;
    int v = (t < SB) ? d_bsum[t] : 0;
    sh[t] = v;
    __syncthreads();
    for (int o = 1; o < 64; o <<= 1) {
        int u = (t >= o) ? sh[t - o] : 0;
        __syncthreads();
        sh[t] += u;
        __syncthreads();
    }
    if (t < SB) d_bsum[t] = sh[t] - v;
    if (t == 63) d_off[NN] = sh[63];
}

__global__ void k_scan3() {  // apply block prefix
    int idx = blockIdx.x * blockDim.x + threadIdx.x;
    if (idx >= NN) return;
    d_off[idx] = d_off[idx] + d_bsum[idx >> 10];
}

// fill: slot index from decrementing cnt_i (which holds degree); cnt_i ends at 0
__global__ void k_fill(const int* __restrict__ ei, int E, int te) {
    int e = blockIdx.x * blockDim.x + threadIdx.x;
    if (e >= te) return;
    int s, d;
    if (e < E) { s = ei[e]; d = ei[E + e]; } else { s = d = e - E; }
    int idx = atomicAdd(&d_cnt_i[d], -1) - 1;
    d_csr[d_off[d] + idx] = s;
}

// ---------------- GAT1 gather: warp per dst node, 2-wide unroll ----------------
__global__ void k_gat1(const float* __restrict__ b1) {
    int t = threadIdx.x, lane = t & 31, w = t >> 5;
    int n = blockIdx.x * 8 + w;
    if (n >= NN) return;
    int head = lane >> 3;
    float sdv = d_sd1[n * 4 + head];
    int beg = d_off[n], end = d_off[n + 1];
    float a0 = 0.f, a1 = 0.f, a2 = 0.f, a3 = 0.f, a4 = 0.f, a5 = 0.f, a6 = 0.f, a7 = 0.f;
    float den = 0.f;
    int i = beg;
    for (; i + 2 <= end; i += 2) {
        int s0 = d_csr[i], s1 = d_csr[i + 1];
        float l0 = d_ss1[s0 * 4 + head], l1 = d_ss1[s1 * 4 + head];
        const float4* hp0 = (const float4*)(d_h1 + (long)s0 * 256);
        const float4* hp1 = (const float4*)(d_h1 + (long)s1 * 256);
        float4 p00 = hp0[lane * 2], p01 = hp0[lane * 2 + 1];
        float4 p10 = hp1[lane * 2], p11 = hp1[lane * 2 + 1];
        float e0 = __expf(lrelu(l0 + sdv));
        float e1 = __expf(lrelu(l1 + sdv));
        den += e0 + e1;
        a0 += p00.x * e0 + p10.x * e1; a1 += p00.y * e0 + p10.y * e1;
        a2 += p00.z * e0 + p10.z * e1; a3 += p00.w * e0 + p10.w * e1;
        a4 += p01.x * e0 + p11.x * e1; a5 += p01.y * e0 + p11.y * e1;
        a6 += p01.z * e0 + p11.z * e1; a7 += p01.w * e0 + p11.w * e1;
    }
    if (i < end) {
        int s = d_csr[i];
        float e = __expf(lrelu(d_ss1[s * 4 + head] + sdv));
        den += e;
        const float4* hp = (const float4*)(d_h1 + (long)s * 256);
        float4 p0 = hp[lane * 2], p1 = hp[lane * 2 + 1];
        a0 += p0.x * e; a1 += p0.y * e; a2 += p0.z * e; a3 += p0.w * e;
        a4 += p1.x * e; a5 += p1.y * e; a6 += p1.z * e; a7 += p1.w * e;
    }
    float inv = 1.f / (den + 1e-16f);
    int c0 = lane * 8;
    float4 o0, o1;
    o0.x = elu(a0 * inv + b1[c0 + 0]);
    o0.y = elu(a1 * inv + b1[c0 + 1]);
    o0.z = elu(a2 * inv + b1[c0 + 2]);
    o0.w = elu(a3 * inv + b1[c0 + 3]);
    o1.x = elu(a4 * inv + b1[c0 + 4]);
    o1.y = elu(a5 * inv + b1[c0 + 5]);
    o1.z = elu(a6 * inv + b1[c0 + 6]);
    o1.w = elu(a7 * inv + b1[c0 + 7]);
    float4* op = (float4*)(d_g1 + (long)n * 256);
    op[lane * 2] = o0;
    op[lane * 2 + 1] = o1;
}

// ---------------- node pass 2: tiled GEMM h2 = g1 @ W2 + att scores + dinv ----------------
__global__ void k_node2(const float* __restrict__ W2,
                        const float* __restrict__ as2, const float* __restrict__ ad2) {
    __shared__ float sA[64][68];
    __shared__ float sB[64][68];
    __shared__ float rs[64][16];
    __shared__ float rd[64][16];
    int t = threadIdx.x;
    int nb = blockIdx.x * 64;
    int tn = t >> 4, tc = t & 15;
    float acc[4][4] = {};
#pragma unroll 1
    for (int kc = 0; kc < 4; kc++) {
#pragma unroll
        for (int j = 0; j < 4; j++) {
            int f4 = t * 4 + j;            // 0..1023
            int row = f4 >> 4;             // 0..63
            int col4 = f4 & 15;            // float4 slot
            int n = nb + row;
            float4 v = (n < NN) ? ((const float4*)(d_g1 + (long)n * 256 + kc * 64))[col4]
                                : make_float4(0.f, 0.f, 0.f, 0.f);
            ((float4*)&sA[row][0])[col4] = v;
            float4 wv = ((const float4*)(W2 + (kc * 64 + row) * 64))[col4];
            ((float4*)&sB[row][0])[col4] = wv;
        }
        __syncthreads();
#pragma unroll 4
        for (int kk = 0; kk < 64; kk++) {
            float4 bv = ((float4*)&sB[kk][0])[tc];
#pragma unroll
            for (int i = 0; i < 4; i++) {
                float av = sA[tn * 4 + i][kk];
                acc[i][0] += av * bv.x; acc[i][1] += av * bv.y;
                acc[i][2] += av * bv.z; acc[i][3] += av * bv.w;
            }
        }
        __syncthreads();
    }
    float4 av2 = ((const float4*)as2)[tc];
    float4 dv2 = ((const float4*)ad2)[tc];
#pragma unroll
    for (int i = 0; i < 4; i++) {
        int n = nb + tn * 4 + i;
        if (n < NN)
            ((float4*)(d_h2 + (long)n * 64))[tc] =
                make_float4(acc[i][0], acc[i][1], acc[i][2], acc[i][3]);
        rs[tn * 4 + i][tc] = acc[i][0] * av2.x + acc[i][1] * av2.y + acc[i][2] * av2.z + acc[i][3] * av2.w;
        rd[tn * 4 + i][tc] = acc[i][0] * dv2.x + acc[i][1] * dv2.y + acc[i][2] * dv2.z + acc[i][3] * dv2.w;
    }
    __syncthreads();
    if (t < 64) {
        int n = nb + t;
        if (n < NN) {
            float ps = 0.f, pd = 0.f;
#pragma unroll
            for (int j = 0; j < 16; j++) { ps += rs[t][j]; pd += rd[t][j]; }
            d_ss2[n] = ps;
            d_sd2[n] = pd;
            d_dinv[n] = rsqrtf((float)(d_off[n + 1] - d_off[n]));
        }
    }
}

// ---------------- GAT2 + GCN gather + fuse + pool: 4 nodes/warp, Wf staged once ----------------
#define G2W 4
__global__ void k_gat2(const float* __restrict__ b2, const float* __restrict__ bg,
                       const float* __restrict__ Wf, const float* __restrict__ bf,
                       const int* __restrict__ batch) {
    __shared__ float sWf[128 * 64];   // 32KB
    __shared__ float sf[8][128];
    __shared__ float sb2[64], sbg[64], sbf[64];
    int t = threadIdx.x, lane = t & 31, w = t >> 5;
    for (int i = t; i < 128 * 64 / 4; i += 256) ((float4*)sWf)[i] = ((const float4*)Wf)[i];
    if (t < 64) { sb2[t] = b2[t]; sbg[t] = bg[t]; sbf[t] = bf[t]; }
    __syncthreads();
#pragma unroll 1
    for (int q = 0; q < G2W; q++) {
        int n = blockIdx.x * (8 * G2W) + w * G2W + q;
        if (n >= NN) continue;
        float sdv = d_sd2[n];
        float dv = d_dinv[n];
        int beg = d_off[n], end = d_off[n + 1];
        float a0 = 0.f, a1 = 0.f, g0 = 0.f, g1 = 0.f, den = 0.f;
        int i = beg;
        for (; i + 2 <= end; i += 2) {
            int s0 = d_csr[i], s1 = d_csr[i + 1];
            float l0 = d_ss2[s0], l1 = d_ss2[s1];
            float di0 = d_dinv[s0], di1 = d_dinv[s1];
            float2 h0 = ((const float2*)(d_h2 + (long)s0 * 64))[lane];
            float2 h1v = ((const float2*)(d_h2 + (long)s1 * 64))[lane];
            float2 x0 = ((const float2*)(d_xg + (long)s0 * 64))[lane];
            float2 x1 = ((const float2*)(d_xg + (long)s1 * 64))[lane];
            float e0 = __expf(lrelu(l0 + sdv));
            float e1 = __expf(lrelu(l1 + sdv));
            den += e0 + e1;
            a0 += h0.x * e0 + h1v.x * e1; a1 += h0.y * e0 + h1v.y * e1;
            float nm0 = di0 * dv, nm1 = di1 * dv;
            g0 += x0.x * nm0 + x1.x * nm1; g1 += x0.y * nm0 + x1.y * nm1;
        }
        if (i < end) {
            int s = d_csr[i];
            float e = __expf(lrelu(d_ss2[s] + sdv));
            den += e;
            float2 h = ((const float2*)(d_h2 + (long)s * 64))[lane];
            a0 += h.x * e; a1 += h.y * e;
            float nm = d_dinv[s] * dv;
            float2 xv = ((const float2*)(d_xg + (long)s * 64))[lane];
            g0 += xv.x * nm; g1 += xv.y * nm;
        }
        float inv = 1.f / (den + 1e-16f);
        int c = 2 * lane;
        sf[w][c]          = elu(a0 * inv + sb2[c]);
        sf[w][c + 1]      = elu(a1 * inv + sb2[c + 1]);
        sf[w][64 + c]     = fmaxf(g0 + sbg[c], 0.f);
        sf[w][64 + c + 1] = fmaxf(g1 + sbg[c + 1], 0.f);
        __syncwarp();
        float acc0 = sbf[c], acc1 = sbf[c + 1];
        const float* sp = sf[w];
#pragma unroll 8
        for (int k = 0; k < 128; k++) {
            float v = sp[k];
            float2 wv = ((const float2*)&sWf[k * 64])[lane];
            acc0 += v * wv.x;
            acc1 += v * wv.y;
        }
        acc0 = fmaxf(acc0, 0.f);
        acc1 = fmaxf(acc1, 0.f);
        int b = batch[n];
        atomicAdd(d_pooled + b * 64 + c, acc0);
        atomicAdd(d_pooled + b * 64 + c + 1, acc1);
        if (lane == 0) atomicAdd(d_gcnt + b, 1.0f);
        __syncwarp();
    }
}

// ---------------- heads: pooled mean -> 2x (relu MLP 64->32->5) ----------------
__global__ void k_head(const float* __restrict__ Wc1, const float* __restrict__ bc1,
                       const float* __restrict__ Wc2, const float* __restrict__ bc2,
                       const float* __restrict__ Wp1, const float* __restrict__ bp1,
                       const float* __restrict__ Wp2, const float* __restrict__ bp2,
                       float* __restrict__ out) {
    int g = blockIdx.x, t = threadIdx.x;
    __shared__ float sp[64], sh[64];
    float cnt = fmaxf(d_gcnt[g], 1.0f);
    sp[t] = d_pooled[g * 64 + t] / cnt;
    __syncthreads();
    float hv;
    if (t < 32) {
        hv = bc1[t];
#pragma unroll 8
        for (int k = 0; k < 64; k++) hv += sp[k] * Wc1[k * 32 + t];
    } else {
        int j = t - 32;
        hv = bp1[j];
#pragma unroll 8
        for (int k = 0; k < 64; k++) hv += sp[k] * Wp1[k * 32 + j];
    }
    sh[t] = fmaxf(hv, 0.f);
    __syncthreads();
    if (t < 5) {
        float o = bc2[t];
#pragma unroll
        for (int j = 0; j < 32; j++) o += sh[j] * Wc2[j * 5 + t];
        out[g * 5 + t] = o;
    } else if (t >= 8 && t < 13) {
        int u = t - 8;
        float o = bp2[u];
#pragma unroll
        for (int j = 0; j < 32; j++) o += sh[32 + j] * Wp2[j * 5 + u];
        out[NG * 5 + g * 5 + u] = o;
    }
}

extern "C" void kernel_launch(void* const* d_in, const int* in_sizes, int n_in,
                              void* d_out, int out_size) {
    const float* x     = (const float*)d_in[0];
    const int*   ei    = (const int*)d_in[1];     // int32 (JAX x64 disabled)
    const int*   batch = (const int*)d_in[3];     // int32
    const float* W1  = (const float*)d_in[4];
    const float* as1 = (const float*)d_in[5];
    const float* ad1 = (const float*)d_in[6];
    const float* b1  = (const float*)d_in[7];
    const float* W2  = (const float*)d_in[8];
    const float* as2 = (const float*)d_in[9];
    const float* ad2 = (const float*)d_in[10];
    const float* b2  = (const float*)d_in[11];
    const float* Wg  = (const float*)d_in[12];
    const float* bg  = (const float*)d_in[13];
    const float* Wf  = (const float*)d_in[14];
    const float* bf  = (const float*)d_in[15];
    const float* Wc1 = (const float*)d_in[16];
    const float* bc1 = (const float*)d_in[17];
    const float* Wc2 = (const float*)d_in[18];
    const float* bc2 = (const float*)d_in[19];
    const float* Wp1 = (const float*)d_in[20];
    const float* bp1 = (const float*)d_in[21];
    const float* Wp2 = (const float*)d_in[22];
    const float* bp2 = (const float*)d_in[23];

    int E  = in_sizes[1] / 2;
    int te = E + NN;
    int eb = (te + 255) / 256;

    k_init<<<512, 256>>>();                                   // 0
    k_count<<<eb, 256>>>(ei, E, te);                          // 1
    k_scan1<<<SB, 1024>>>();                                  // 2
    k_h1<<<(NN + H1N - 1) / H1N, 256>>>(x, W1, as1, ad1, Wg); // 3 <- profiled
    k_scan2<<<1, 64>>>();                                     // 4
    k_scan3<<<(NN + 255) / 256, 256>>>();                     // 5
    k_fill<<<eb, 256>>>(ei, E, te);                           // 6
    k_gat1<<<(NN + 7) / 8, 256>>>(b1);                        // 7
    k_node2<<<(NN + 63) / 64, 256>>>(W2, as2, ad2);           // 8
    k_gat2<<<(NN + G2W * 8 - 1) / (G2W * 8), 256>>>(b2, bg, Wf, bf, batch);  // 9
    k_head<<<NG, 64>>>(Wc1, bc1, Wc2, bc2, Wp1, bp1, Wp2, bp2, (float*)d_out); // 10
}

// round 7
// speedup vs baseline: 1.6083x; 1.1328x over previous
#include <cuda_runtime.h>
#include <math.h>

#define NN 50000
#define NE_MAX 800000
#define TE_MAX (NE_MAX + NN)
#define NG 128
#define SB 49   // scan blocks (49*1024 >= 50000)

// ---------------- scratch (device globals; no allocation) ----------------
__device__ __align__(16) float d_h1[NN * 256];    // x@W1 (4 heads x 64ch)
__device__ __align__(16) float d_g1[NN * 256];    // elu(gat1 + b1)
__device__ __align__(16) float d_ss1[NN * 4];
__device__ __align__(16) float d_sd1[NN * 4];
__device__ __align__(16) float d_h2[NN * 64];     // g1@W2
__device__ __align__(16) float d_xg[NN * 64];     // x@Wg
__device__ float d_ss2[NN];
__device__ float d_sd2[NN];
__device__ float d_dinv[NN];
__device__ float d_pooled[NG * 64];
__device__ float d_gcnt[NG];
__device__ float d_A1s[14 * 4];   // W1 @ as1 (per head), folded score matrices
__device__ float d_A1d[14 * 4];
// CSR by destination
__device__ int d_cnt_i[NN];
__device__ int d_off[NN + 1];
__device__ int d_csr[TE_MAX];
__device__ int d_bsum[64];

__device__ __forceinline__ float lrelu(float u) { return u > 0.f ? u : 0.2f * u; }
__device__ __forceinline__ float elu(float u)   { return u > 0.f ? u : expm1f(u); }

// ---------------- init: zero counters / accumulators ----------------
__global__ void k_init() {
    int i  = blockIdx.x * blockDim.x + threadIdx.x;
    int st = gridDim.x * blockDim.x;
    for (int j = i; j < NN; j += st) d_cnt_i[j] = 0;
    for (int j = i; j < NG * 64; j += st) d_pooled[j] = 0.f;
    for (int j = i; j < NG; j += st) d_gcnt[j] = 0.f;
}

// ---------------- prep: fold attention vectors through W1 (14x4 each) ----------------
__global__ void k_prep(const float* __restrict__ W1,
                       const float* __restrict__ as1, const float* __restrict__ ad1) {
    int t = threadIdx.x;
    if (t >= 56) return;
    int k = t >> 2, h = t & 3;
    float ss = 0.f, sd = 0.f;
#pragma unroll 8
    for (int c = 0; c < 64; c++) {
        float w = W1[k * 256 + h * 64 + c];
        ss += w * as1[h * 64 + c];
        sd += w * ad1[h * 64 + c];
    }
    d_A1s[k * 4 + h] = ss;
    d_A1d[k * 4 + h] = sd;
}

// ---------------- CSR count ----------------
__global__ void k_count(const int* __restrict__ ei, int E, int te) {
    int e = blockIdx.x * blockDim.x + threadIdx.x;
    if (e >= te) return;
    int d = (e < E) ? ei[E + e] : (e - E);
    atomicAdd(&d_cnt_i[d], 1);
}

// ---------------- node pass 1: weights in registers, 32 nodes/block ----------------
#define H1N 32
__global__ void k_h1(const float* __restrict__ x, const float* __restrict__ W1,
                     const float* __restrict__ Wg) {
    __shared__ float sx[H1N][14];
    __shared__ float sA1s[14][4], sA1d[14][4];
    int t = threadIdx.x;
    int nb = blockIdx.x * H1N;
    // weights into registers: t<256 -> W1 col t; t>=256 -> Wg col (t-256)
    float w[14];
    if (t < 256) {
#pragma unroll
        for (int k = 0; k < 14; k++) w[k] = W1[k * 256 + t];
    } else {
        int c = t - 256;
#pragma unroll
        for (int k = 0; k < 14; k++) w[k] = Wg[k * 64 + c];
    }
    if (t < 56) {
        ((float*)sA1s)[t] = d_A1s[t];
        ((float*)sA1d)[t] = d_A1d[t];
    }
    for (int i = t; i < H1N * 14; i += 320) {
        int nn = i / 14, k = i % 14;
        int n = nb + nn;
        sx[nn][k] = (n < NN) ? x[n * 14 + k] : 0.f;
    }
    __syncthreads();
#pragma unroll 1
    for (int i = 0; i < H1N; i++) {
        int n = nb + i;
        if (n >= NN) break;
        float acc = 0.f;
#pragma unroll
        for (int k = 0; k < 14; k++) acc += w[k] * sx[i][k];
        if (t < 256) d_h1[(long)n * 256 + t] = acc;
        else d_xg[(long)n * 64 + (t - 256)] = acc;
    }
    // scores: 128 threads cover 32 nodes x 4 heads
    if (t < H1N * 4) {
        int nn = t >> 2, h = t & 3;
        int n = nb + nn;
        if (n < NN) {
            float ss = 0.f, sd = 0.f;
#pragma unroll
            for (int k = 0; k < 14; k++) {
                float xv = sx[nn][k];
                ss += xv * sA1s[k][h];
                sd += xv * sA1d[k][h];
            }
            d_ss1[n * 4 + h] = ss;
            d_sd1[n * 4 + h] = sd;
        }
    }
}

__global__ void k_scan1() {  // grid SB, 1024 thr: per-block exclusive scan + block sums
    __shared__ int sh[1024];
    int t = threadIdx.x;
    int idx = blockIdx.x * 1024 + t;
    int v = (idx < NN) ? d_cnt_i[idx] : 0;
    sh[t] = v;
    __syncthreads();
    for (int o = 1; o < 1024; o <<= 1) {
        int u = (t >= o) ? sh[t - o] : 0;
        __syncthreads();
        sh[t] += u;
        __syncthreads();
    }
    if (idx < NN) d_off[idx] = sh[t] - v;   // exclusive within block
    if (t == 1023) d_bsum[blockIdx.x] = sh[1023];
}

__global__ void k_scan2() {  // 1 block, 64 thr: exclusive scan of block sums
    __shared__ int sh[64];
    int t = threadIdx.x;
    int v = (t < SB) ? d_bsum[t] : 0;
    sh[t] = v;
    __syncthreads();
    for (int o = 1; o < 64; o <<= 1) {
        int u = (t >= o) ? sh[t - o] : 0;
        __syncthreads();
        sh[t] += u;
        __syncthreads();
    }
    if (t < SB) d_bsum[t] = sh[t] - v;
    if (t == 63) d_off[NN] = sh[63];
}

__global__ void k_scan3() {  // apply block prefix; dinv from degree (cnt_i intact here)
    int idx = blockIdx.x * blockDim.x + threadIdx.x;
    if (idx >= NN) return;
    d_off[idx] = d_off[idx] + d_bsum[idx >> 10];
    d_dinv[idx] = rsqrtf((float)d_cnt_i[idx]);
}

// fill: slot index from decrementing cnt_i (which holds degree); cnt_i ends at 0
__global__ void k_fill(const int* __restrict__ ei, int E, int te) {
    int e = blockIdx.x * blockDim.x + threadIdx.x;
    if (e >= te) return;
    int s, d;
    if (e < E) { s = ei[e]; d = ei[E + e]; } else { s = d = e - E; }
    int idx = atomicAdd(&d_cnt_i[d], -1) - 1;
    d_csr[d_off[d] + idx] = s;
}

// ---------------- GAT1 gather: warp per dst node, 2-wide unroll ----------------
__global__ void k_gat1(const float* __restrict__ b1) {
    int t = threadIdx.x, lane = t & 31, w = t >> 5;
    int n = blockIdx.x * 8 + w;
    if (n >= NN) return;
    int head = lane >> 3;
    float sdv = d_sd1[n * 4 + head];
    int beg = d_off[n], end = d_off[n + 1];
    float a0 = 0.f, a1 = 0.f, a2 = 0.f, a3 = 0.f, a4 = 0.f, a5 = 0.f, a6 = 0.f, a7 = 0.f;
    float den = 0.f;
    int i = beg;
    for (; i + 2 <= end; i += 2) {
        int s0 = d_csr[i], s1 = d_csr[i + 1];
        float l0 = d_ss1[s0 * 4 + head], l1 = d_ss1[s1 * 4 + head];
        const float4* hp0 = (const float4*)(d_h1 + (long)s0 * 256);
        const float4* hp1 = (const float4*)(d_h1 + (long)s1 * 256);
        float4 p00 = hp0[lane * 2], p01 = hp0[lane * 2 + 1];
        float4 p10 = hp1[lane * 2], p11 = hp1[lane * 2 + 1];
        float e0 = __expf(lrelu(l0 + sdv));
        float e1 = __expf(lrelu(l1 + sdv));
        den += e0 + e1;
        a0 += p00.x * e0 + p10.x * e1; a1 += p00.y * e0 + p10.y * e1;
        a2 += p00.z * e0 + p10.z * e1; a3 += p00.w * e0 + p10.w * e1;
        a4 += p01.x * e0 + p11.x * e1; a5 += p01.y * e0 + p11.y * e1;
        a6 += p01.z * e0 + p11.z * e1; a7 += p01.w * e0 + p11.w * e1;
    }
    if (i < end) {
        int s = d_csr[i];
        float e = __expf(lrelu(d_ss1[s * 4 + head] + sdv));
        den += e;
        const float4* hp = (const float4*)(d_h1 + (long)s * 256);
        float4 p0 = hp[lane * 2], p1 = hp[lane * 2 + 1];
        a0 += p0.x * e; a1 += p0.y * e; a2 += p0.z * e; a3 += p0.w * e;
        a4 += p1.x * e; a5 += p1.y * e; a6 += p1.z * e; a7 += p1.w * e;
    }
    float inv = 1.f / (den + 1e-16f);
    int c0 = lane * 8;
    float4 o0, o1;
    o0.x = elu(a0 * inv + b1[c0 + 0]);
    o0.y = elu(a1 * inv + b1[c0 + 1]);
    o0.z = elu(a2 * inv + b1[c0 + 2]);
    o0.w = elu(a3 * inv + b1[c0 + 3]);
    o1.x = elu(a4 * inv + b1[c0 + 4]);
    o1.y = elu(a5 * inv + b1[c0 + 5]);
    o1.z = elu(a6 * inv + b1[c0 + 6]);
    o1.w = elu(a7 * inv + b1[c0 + 7]);
    float4* op = (float4*)(d_g1 + (long)n * 256);
    op[lane * 2] = o0;
    op[lane * 2 + 1] = o1;
}

// ---------------- node pass 2: tiled GEMM h2 = g1 @ W2 + att scores ----------------
__global__ void k_node2(const float* __restrict__ W2,
                        const float* __restrict__ as2, const float* __restrict__ ad2) {
    __shared__ float sA[64][68];
    __shared__ float sB[64][68];
    __shared__ float rs[64][16];
    __shared__ float rd[64][16];
    int t = threadIdx.x;
    int nb = blockIdx.x * 64;
    int tn = t >> 4, tc = t & 15;
    float acc[4][4] = {};
#pragma unroll 1
    for (int kc = 0; kc < 4; kc++) {
#pragma unroll
        for (int j = 0; j < 4; j++) {
            int f4 = t * 4 + j;            // 0..1023
            int row = f4 >> 4;             // 0..63
            int col4 = f4 & 15;            // float4 slot
            int n = nb + row;
            float4 v = (n < NN) ? ((const float4*)(d_g1 + (long)n * 256 + kc * 64))[col4]
                                : make_float4(0.f, 0.f, 0.f, 0.f);
            ((float4*)&sA[row][0])[col4] = v;
            float4 wv = ((const float4*)(W2 + (kc * 64 + row) * 64))[col4];
            ((float4*)&sB[row][0])[col4] = wv;
        }
        __syncthreads();
#pragma unroll 4
        for (int kk = 0; kk < 64; kk++) {
            float4 bv = ((float4*)&sB[kk][0])[tc];
#pragma unroll
            for (int i = 0; i < 4; i++) {
                float av = sA[tn * 4 + i][kk];
                acc[i][0] += av * bv.x; acc[i][1] += av * bv.y;
                acc[i][2] += av * bv.z; acc[i][3] += av * bv.w;
            }
        }
        __syncthreads();
    }
    float4 av2 = ((const float4*)as2)[tc];
    float4 dv2 = ((const float4*)ad2)[tc];
#pragma unroll
    for (int i = 0; i < 4; i++) {
        int n = nb + tn * 4 + i;
        if (n < NN)
            ((float4*)(d_h2 + (long)n * 64))[tc] =
                make_float4(acc[i][0], acc[i][1], acc[i][2], acc[i][3]);
        rs[tn * 4 + i][tc] = acc[i][0] * av2.x + acc[i][1] * av2.y + acc[i][2] * av2.z + acc[i][3] * av2.w;
        rd[tn * 4 + i][tc] = acc[i][0] * dv2.x + acc[i][1] * dv2.y + acc[i][2] * dv2.z + acc[i][3] * dv2.w;
    }
    __syncthreads();
    if (t < 64) {
        int n = nb + t;
        if (n < NN) {
            float ps = 0.f, pd = 0.f;
#pragma unroll
            for (int j = 0; j < 16; j++) { ps += rs[t][j]; pd += rd[t][j]; }
            d_ss2[n] = ps;
            d_sd2[n] = pd;
        }
    }
}

// ---------------- GAT2 + GCN gather + fuse + pool: 4 nodes/warp, Wf staged once ----------------
#define G2W 4
__global__ void k_gat2(const float* __restrict__ b2, const float* __restrict__ bg,
                       const float* __restrict__ Wf, const float* __restrict__ bf,
                       const int* __restrict__ batch) {
    __shared__ float sWf[128 * 64];   // 32KB
    __shared__ float sf[8][128];
    __shared__ float sb2[64], sbg[64], sbf[64];
    int t = threadIdx.x, lane = t & 31, w = t >> 5;
    for (int i = t; i < 128 * 64 / 4; i += 256) ((float4*)sWf)[i] = ((const float4*)Wf)[i];
    if (t < 64) { sb2[t] = b2[t]; sbg[t] = bg[t]; sbf[t] = bf[t]; }
    __syncthreads();
#pragma unroll 1
    for (int q = 0; q < G2W; q++) {
        int n = blockIdx.x * (8 * G2W) + w * G2W + q;
        if (n >= NN) continue;
        float sdv = d_sd2[n];
        float dv = d_dinv[n];
        int beg = d_off[n], end = d_off[n + 1];
        float a0 = 0.f, a1 = 0.f, g0 = 0.f, g1 = 0.f, den = 0.f;
        int i = beg;
        for (; i + 2 <= end; i += 2) {
            int s0 = d_csr[i], s1 = d_csr[i + 1];
            float l0 = d_ss2[s0], l1 = d_ss2[s1];
            float di0 = d_dinv[s0], di1 = d_dinv[s1];
            float2 h0 = ((const float2*)(d_h2 + (long)s0 * 64))[lane];
            float2 h1v = ((const float2*)(d_h2 + (long)s1 * 64))[lane];
            float2 x0 = ((const float2*)(d_xg + (long)s0 * 64))[lane];
            float2 x1 = ((const float2*)(d_xg + (long)s1 * 64))[lane];
            float e0 = __expf(lrelu(l0 + sdv));
            float e1 = __expf(lrelu(l1 + sdv));
            den += e0 + e1;
            a0 += h0.x * e0 + h1v.x * e1; a1 += h0.y * e0 + h1v.y * e1;
            float nm0 = di0 * dv, nm1 = di1 * dv;
            g0 += x0.x * nm0 + x1.x * nm1; g1 += x0.y * nm0 + x1.y * nm1;
        }
        if (i < end) {
            int s = d_csr[i];
            float e = __expf(lrelu(d_ss2[s] + sdv));
            den += e;
            float2 h = ((const float2*)(d_h2 + (long)s * 64))[lane];
            a0 += h.x * e; a1 += h.y * e;
            float nm = d_dinv[s] * dv;
            float2 xv = ((const float2*)(d_xg + (long)s * 64))[lane];
            g0 += xv.x * nm; g1 += xv.y * nm;
        }
        float inv = 1.f / (den + 1e-16f);
        int c = 2 * lane;
        sf[w][c]          = elu(a0 * inv + sb2[c]);
        sf[w][c + 1]      = elu(a1 * inv + sb2[c + 1]);
        sf[w][64 + c]     = fmaxf(g0 + sbg[c], 0.f);
        sf[w][64 + c + 1] = fmaxf(g1 + sbg[c + 1], 0.f);
        __syncwarp();
        float acc0 = sbf[c], acc1 = sbf[c + 1];
        const float* sp = sf[w];
#pragma unroll 8
        for (int k = 0; k < 128; k++) {
            float v = sp[k];
            float2 wv = ((const float2*)&sWf[k * 64])[lane];
            acc0 += v * wv.x;
            acc1 += v * wv.y;
        }
        acc0 = fmaxf(acc0, 0.f);
        acc1 = fmaxf(acc1, 0.f);
        int b = batch[n];
        atomicAdd(d_pooled + b * 64 + c, acc0);
        atomicAdd(d_pooled + b * 64 + c + 1, acc1);
        if (lane == 0) atomicAdd(d_gcnt + b, 1.0f);
        __syncwarp();
    }
}

// ---------------- heads: pooled mean -> 2x (relu MLP 64->32->5) ----------------
__global__ void k_head(const float* __restrict__ Wc1, const float* __restrict__ bc1,
                       const float* __restrict__ Wc2, const float* __restrict__ bc2,
                       const float* __restrict__ Wp1, const float* __restrict__ bp1,
                       const float* __restrict__ Wp2, const float* __restrict__ bp2,
                       float* __restrict__ out) {
    int g = blockIdx.x, t = threadIdx.x;
    __shared__ float sp[64], sh[64];
    float cnt = fmaxf(d_gcnt[g], 1.0f);
    sp[t] = d_pooled[g * 64 + t] / cnt;
    __syncthreads();
    float hv;
    if (t < 32) {
        hv = bc1[t];
#pragma unroll 8
        for (int k = 0; k < 64; k++) hv += sp[k] * Wc1[k * 32 + t];
    } else {
        int j = t - 32;
        hv = bp1[j];
#pragma unroll 8
        for (int k = 0; k < 64; k++) hv += sp[k] * Wp1[k * 32 + j];
    }
    sh[t] = fmaxf(hv, 0.f);
    __syncthreads();
    if (t < 5) {
        float o = bc2[t];
#pragma unroll
        for (int j = 0; j < 32; j++) o += sh[j] * Wc2[j * 5 + t];
        out[g * 5 + t] = o;
    } else if (t >= 8 && t < 13) {
        int u = t - 8;
        float o = bp2[u];
#pragma unroll
        for (int j = 0; j < 32; j++) o += sh[32 + j] * Wp2[j * 5 + u];
        out[NG * 5 + g * 5 + u] = o;
    }
}

extern "C" void kernel_launch(void* const* d_in, const int* in_sizes, int n_in,
                              void* d_out, int out_size) {
    const float* x     = (const float*)d_in[0];
    const int*   ei    = (const int*)d_in[1];     // int32 (JAX x64 disabled)
    const int*   batch = (const int*)d_in[3];     // int32
    const float* W1  = (const float*)d_in[4];
    const float* as1 = (const float*)d_in[5];
    const float* ad1 = (const float*)d_in[6];
    const float* b1  = (const float*)d_in[7];
    const float* W2  = (const float*)d_in[8];
    const float* as2 = (const float*)d_in[9];
    const float* ad2 = (const float*)d_in[10];
    const float* b2  = (const float*)d_in[11];
    const float* Wg  = (const float*)d_in[12];
    const float* bg  = (const float*)d_in[13];
    const float* Wf  = (const float*)d_in[14];
    const float* bf  = (const float*)d_in[15];
    const float* Wc1 = (const float*)d_in[16];
    const float* bc1 = (const float*)d_in[17];
    const float* Wc2 = (const float*)d_in[18];
    const float* bc2 = (const float*)d_in[19];
    const float* Wp1 = (const float*)d_in[20];
    const float* bp1 = (const float*)d_in[21];
    const float* Wp2 = (const float*)d_in[22];
    const float* bp2 = (const float*)d_in[23];

    int E  = in_sizes[1] / 2;
    int te = E + NN;
    int eb = (te + 255) / 256;

    k_init<<<512, 256>>>();                                   // 0
    k_prep<<<1, 64>>>(W1, as1, ad1);                          // 1
    k_count<<<eb, 256>>>(ei, E, te);                          // 2
    k_h1<<<(NN + H1N - 1) / H1N, 320>>>(x, W1, Wg);           // 3 <- profiled
    k_scan1<<<SB, 1024>>>();                                  // 4
    k_scan2<<<1, 64>>>();                                     // 5
    k_scan3<<<(NN + 255) / 256, 256>>>();                     // 6
    k_fill<<<eb, 256>>>(ei, E, te);                           // 7
    k_gat1<<<(NN + 7) / 8, 256>>>(b1);                        // 8
    k_node2<<<(NN + 63) / 64, 256>>>(W2, as2, ad2);           // 9
    k_gat2<<<(NN + G2W * 8 - 1) / (G2W * 8), 256>>>(b2, bg, Wf, bf, batch);  // 10
    k_head<<<NG, 64>>>(Wc1, bc1, Wc2, bc2, Wp1, bp1, Wp2, bp2, (float*)d_out); // 11
}

// round 9
// speedup vs baseline: 1.6866x; 1.0487x over previous
#include <cuda_runtime.h>
#include <math.h>

#define NN 50000
#define NE_MAX 800000
#define TE_MAX (NE_MAX + NN)
#define NG 128
#define SB 49   // scan blocks (49*1024 >= 50000)

// ---------------- scratch (device globals; no allocation) ----------------
__device__ __align__(16) float d_g1[NN * 256];    // elu(gat1 + b1)
__device__ __align__(16) float d_ss1[NN * 4];
__device__ __align__(16) float d_sd1[NN * 4];
__device__ __align__(16) float d_h2[NN * 64];     // g1@W2
__device__ __align__(16) float d_gc[NN * 64];     // relu(GCN + bg)
__device__ __align__(16) float d_y[NN * 56];      // per-node per-head weighted x sums
__device__ __align__(16) float d_den[NN * 4];     // softmax denominators (4 heads)
__device__ float d_z[NN * 14];                    // per-node GCN-weighted x sums
__device__ float d_ss2[NN];
__device__ float d_sd2[NN];
__device__ float d_dinv[NN];
__device__ float d_pooled[NG * 64];
__device__ float d_gcnt[NG];
__device__ float d_A1s[14 * 4];   // W1 @ as1 (per head), folded score matrices
__device__ float d_A1d[14 * 4];
// CSR by destination
__device__ int d_cnt_i[NN];
__device__ int d_off[NN + 1];
__device__ int d_csr[TE_MAX];
__device__ int d_bsum[64];

__device__ __forceinline__ float lrelu(float u) { return u > 0.f ? u : 0.2f * u; }
__device__ __forceinline__ float elu(float u)   { return u > 0.f ? u : expm1f(u); }

// ---------------- init: zero counters / accumulators ----------------
__global__ void k_init() {
    int i  = blockIdx.x * blockDim.x + threadIdx.x;
    int st = gridDim.x * blockDim.x;
    for (int j = i; j < NN; j += st) d_cnt_i[j] = 0;
    for (int j = i; j < NG * 64; j += st) d_pooled[j] = 0.f;
    for (int j = i; j < NG; j += st) d_gcnt[j] = 0.f;
}

// ---------------- prep: fold attention vectors through W1 (14x4 each) ----------------
__global__ void k_prep(const float* __restrict__ W1,
                       const float* __restrict__ as1, const float* __restrict__ ad1) {
    int t = threadIdx.x;
    if (t >= 56) return;
    int k = t >> 2, h = t & 3;
    float ss = 0.f, sd = 0.f;
#pragma unroll 8
    for (int c = 0; c < 64; c++) {
        float w = W1[k * 256 + h * 64 + c];
        ss += w * as1[h * 64 + c];
        sd += w * ad1[h * 64 + c];
    }
    d_A1s[k * 4 + h] = ss;
    d_A1d[k * 4 + h] = sd;
}

// ---------------- CSR count ----------------
__global__ void k_count(const int* __restrict__ ei, int E, int te) {
    int e = blockIdx.x * blockDim.x + threadIdx.x;
    if (e >= te) return;
    int d = (e < E) ? ei[E + e] : (e - E);
    atomicAdd(&d_cnt_i[d], 1);
}

// ---------------- GAT1 scores directly from x via folded matrices ----------------
__global__ void k_h1x(const float* __restrict__ x) {
    __shared__ float sAs[56], sAd[56];
    int t = threadIdx.x;
    if (t < 56) { sAs[t] = d_A1s[t]; sAd[t] = d_A1d[t]; }
    __syncthreads();
    int n = blockIdx.x * blockDim.x + t;
    if (n >= NN) return;
    float xv[14];
#pragma unroll
    for (int k = 0; k < 14; k++) xv[k] = x[n * 14 + k];
    float s4[4] = {0.f, 0.f, 0.f, 0.f}, p4[4] = {0.f, 0.f, 0.f, 0.f};
#pragma unroll
    for (int k = 0; k < 14; k++) {
#pragma unroll
        for (int h = 0; h < 4; h++) {
            s4[h] += xv[k] * sAs[k * 4 + h];
            p4[h] += xv[k] * sAd[k * 4 + h];
        }
    }
    ((float4*)d_ss1)[n] = make_float4(s4[0], s4[1], s4[2], s4[3]);
    ((float4*)d_sd1)[n] = make_float4(p4[0], p4[1], p4[2], p4[3]);
}

__global__ void k_scan1() {  // grid SB, 1024 thr: per-block exclusive scan + block sums
    __shared__ int sh[1024];
    int t = threadIdx.x;
    int idx = blockIdx.x * 1024 + t;
    int v = (idx < NN) ? d_cnt_i[idx] : 0;
    sh[t] = v;
    __syncthreads();
    for (int o = 1; o < 1024; o <<= 1) {
        int u = (t >= o) ? sh[t - o] : 0;
        __syncthreads();
        sh[t] += u;
        __syncthreads();
    }
    if (idx < NN) d_off[idx] = sh[t] - v;   // exclusive within block
    if (t == 1023) d_bsum[blockIdx.x] = sh[1023];
}

__global__ void k_scan2() {  // 1 block, 64 thr: exclusive scan of block sums
    __shared__ int sh[64];
    int t = threadIdx.x;
    int v = (t < SB) ? d_bsum[t] : 0;
    sh[t] = v;
    __syncthreads();
    for (int o = 1; o < 64; o <<= 1) {
        int u = (t >= o) ? sh[t - o] : 0;
        __syncthreads();
        sh[t] += u;
        __syncthreads();
    }
    if (t < SB) d_bsum[t] = sh[t] - v;
    if (t == 63) d_off[NN] = sh[63];
}

__global__ void k_scan3() {  // apply block prefix; dinv from degree (cnt_i intact here)
    int idx = blockIdx.x * blockDim.x + threadIdx.x;
    if (idx >= NN) return;
    d_off[idx] = d_off[idx] + d_bsum[idx >> 10];
    d_dinv[idx] = rsqrtf((float)d_cnt_i[idx]);
}

// fill: slot index from decrementing cnt_i (which holds degree); cnt_i ends at 0
__global__ void k_fill(const int* __restrict__ ei, int E, int te) {
    int e = blockIdx.x * blockDim.x + threadIdx.x;
    if (e >= te) return;
    int s, d;
    if (e < E) { s = ei[e]; d = ei[E + e]; } else { s = d = e - E; }
    int idx = atomicAdd(&d_cnt_i[d], -1) - 1;
    d_csr[d_off[d] + idx] = s;
}

// ---------------- gather1: 4 threads/node (1 per head); accumulates 14-dim x sums ----------------
// y[n,h,:] = sum_s e_sh * x[s,:], den[n,h] = sum e;  z[n,:] = sum_s dinv[s]*x[s,:]
__global__ void k_gather1(const float* __restrict__ x) {
    int gid = blockIdx.x * blockDim.x + threadIdx.x;
    int n = gid >> 2, h = gid & 3;
    if (n >= NN) return;
    float sdv = d_sd1[n * 4 + h];
    int beg = d_off[n], end = d_off[n + 1];
    float y[14] = {0.f, 0.f, 0.f, 0.f, 0.f, 0.f, 0.f, 0.f, 0.f, 0.f, 0.f, 0.f, 0.f, 0.f};
    float z[14] = {0.f, 0.f, 0.f, 0.f, 0.f, 0.f, 0.f, 0.f, 0.f, 0.f, 0.f, 0.f, 0.f, 0.f};
    float den = 0.f;
    for (int i = beg; i < end; i++) {
        int s = d_csr[i];
        float e = __expf(lrelu(d_ss1[s * 4 + h] + sdv));
        den += e;
        float dis = (h == 0) ? d_dinv[s] : 0.f;
        const float* xr = x + s * 14;
#pragma unroll
        for (int k = 0; k < 14; k++) {
            float xv = __ldg(xr + k);
            y[k] += e * xv;
            z[k] += dis * xv;
        }
    }
    float* yp = d_y + n * 56 + h * 14;
#pragma unroll
    for (int k = 0; k < 14; k++) yp[k] = y[k];
    d_den[n * 4 + h] = den;
    if (h == 0) {
#pragma unroll
        for (int k = 0; k < 14; k++) d_z[n * 14 + k] = z[k];
    }
}

// ---------------- g1mid: g1 = elu((y/den)@W1 + b1); gc = relu(dinv*(z@Wg) + bg) ----------------
#define GMN 32
__global__ void k_g1mid(const float* __restrict__ W1, const float* __restrict__ b1,
                        const float* __restrict__ Wg, const float* __restrict__ bg) {
    __shared__ float sW1[14 * 256];
    __shared__ float sWg[14 * 64];
    __shared__ float sb1[256], sbg[64];
    __shared__ float sY[4][56];
    __shared__ float sDen[4][4];
    __shared__ float sZ[4][14];
    __shared__ float sDv[4];
    int t = threadIdx.x;
    int nb = blockIdx.x * GMN;
    for (int i = t; i < 14 * 256; i += 256) sW1[i] = W1[i];
    for (int i = t; i < 14 * 64; i += 256) sWg[i] = Wg[i];
    sb1[t] = b1[t];
    if (t < 64) sbg[t] = bg[t];
    __syncthreads();
    int g = t >> 6, cc = t & 63;
#pragma unroll 1
    for (int it = 0; it < GMN / 4; it++) {
        int n = nb + it * 4 + g;
        if (n < NN) {
            if (cc < 56) sY[g][cc] = d_y[n * 56 + cc];
            else if (cc < 60) sDen[g][cc - 56] = d_den[n * 4 + (cc - 56)];
            else if (cc == 60) sDv[g] = d_dinv[n];
            if (cc < 14) sZ[g][cc] = d_z[n * 14 + cc];
        }
        __syncthreads();
        if (n < NN) {
#pragma unroll
            for (int h = 0; h < 4; h++) {
                float acc = 0.f;
#pragma unroll
                for (int k = 0; k < 14; k++) acc += sY[g][h * 14 + k] * sW1[k * 256 + h * 64 + cc];
                float inv = 1.f / (sDen[g][h] + 1e-16f);
                d_g1[(long)n * 256 + h * 64 + cc] = elu(acc * inv + sb1[h * 64 + cc]);
            }
            float accg = 0.f;
#pragma unroll
            for (int k = 0; k < 14; k++) accg += sZ[g][k] * sWg[k * 64 + cc];
            d_gc[(long)n * 64 + cc] = fmaxf(sDv[g] * accg + sbg[cc], 0.f);
        }
        __syncthreads();
    }
}

// ---------------- node pass 2: tiled GEMM h2 = g1 @ W2 + att scores ----------------
__global__ void k_node2(const float* __restrict__ W2,
                        const float* __restrict__ as2, const float* __restrict__ ad2) {
    __shared__ float sA[64][68];
    __shared__ float sB[64][68];
    __shared__ float rs[64][16];
    __shared__ float rd[64][16];
    int t = threadIdx.x;
    int nb = blockIdx.x * 64;
    int tn = t >> 4, tc = t & 15;
    float acc[4][4] = {};
#pragma unroll 1
    for (int kc = 0; kc < 4; kc++) {
#pragma unroll
        for (int j = 0; j < 4; j++) {
            int f4 = t * 4 + j;            // 0..1023
            int row = f4 >> 4;             // 0..63
            int col4 = f4 & 15;            // float4 slot
            int n = nb + row;
            float4 v = (n < NN) ? ((const float4*)(d_g1 + (long)n * 256 + kc * 64))[col4]
                                : make_float4(0.f, 0.f, 0.f, 0.f);
            ((float4*)&sA[row][0])[col4] = v;
            float4 wv = ((const float4*)(W2 + (kc * 64 + row) * 64))[col4];
            ((float4*)&sB[row][0])[col4] = wv;
        }
        __syncthreads();
#pragma unroll 4
        for (int kk = 0; kk < 64; kk++) {
            float4 bv = ((float4*)&sB[kk][0])[tc];
#pragma unroll
            for (int i = 0; i < 4; i++) {
                float av = sA[tn * 4 + i][kk];
                acc[i][0] += av * bv.x; acc[i][1] += av * bv.y;
                acc[i][2] += av * bv.z; acc[i][3] += av * bv.w;
            }
        }
        __syncthreads();
    }
    float4 av2 = ((const float4*)as2)[tc];
    float4 dv2 = ((const float4*)ad2)[tc];
#pragma unroll
    for (int i = 0; i < 4; i++) {
        int n = nb + tn * 4 + i;
        if (n < NN)
            ((float4*)(d_h2 + (long)n * 64))[tc] =
                make_float4(acc[i][0], acc[i][1], acc[i][2], acc[i][3]);
        rs[tn * 4 + i][tc] = acc[i][0] * av2.x + acc[i][1] * av2.y + acc[i][2] * av2.z + acc[i][3] * av2.w;
        rd[tn * 4 + i][tc] = acc[i][0] * dv2.x + acc[i][1] * dv2.y + acc[i][2] * dv2.z + acc[i][3] * dv2.w;
    }
    __syncthreads();
    if (t < 64) {
        int n = nb + t;
        if (n < NN) {
            float ps = 0.f, pd = 0.f;
#pragma unroll
            for (int j = 0; j < 16; j++) { ps += rs[t][j]; pd += rd[t][j]; }
            d_ss2[n] = ps;
            d_sd2[n] = pd;
        }
    }
}

// ---------------- GAT2 gather + fuse + pool: 4 nodes/warp, Wf staged once ----------------
#define G2W 4
__global__ void k_gat2(const float* __restrict__ b2, const float* __restrict__ bf,
                       const float* __restrict__ Wf,
                       const int* __restrict__ batch) {
    __shared__ float sWf[128 * 64];   // 32KB
    __shared__ float sf[8][128];
    __shared__ float sb2[64], sbf[64];
    int t = threadIdx.x, lane = t & 31, w = t >> 5;
    for (int i = t; i < 128 * 64 / 4; i += 256) ((float4*)sWf)[i] = ((const float4*)Wf)[i];
    if (t < 64) { sb2[t] = b2[t]; sbf[t] = bf[t]; }
    __syncthreads();
#pragma unroll 1
    for (int q = 0; q < G2W; q++) {
        int n = blockIdx.x * (8 * G2W) + w * G2W + q;
        if (n >= NN) continue;
        float sdv = d_sd2[n];
        int beg = d_off[n], end = d_off[n + 1];
        float a0 = 0.f, a1 = 0.f, den = 0.f;
        int i = beg;
        for (; i + 2 <= end; i += 2) {
            int s0 = d_csr[i], s1 = d_csr[i + 1];
            float l0 = d_ss2[s0], l1 = d_ss2[s1];
            float2 h0 = ((const float2*)(d_h2 + (long)s0 * 64))[lane];
            float2 h1v = ((const float2*)(d_h2 + (long)s1 * 64))[lane];
            float e0 = __expf(lrelu(l0 + sdv));
            float e1 = __expf(lrelu(l1 + sdv));
            den += e0 + e1;
            a0 += h0.x * e0 + h1v.x * e1;
            a1 += h0.y * e0 + h1v.y * e1;
        }
        if (i < end) {
            int s = d_csr[i];
            float e = __expf(lrelu(d_ss2[s] + sdv));
            den += e;
            float2 h = ((const float2*)(d_h2 + (long)s * 64))[lane];
            a0 += h.x * e; a1 += h.y * e;
        }
        float inv = 1.f / (den + 1e-16f);
        int c = 2 * lane;
        float2 gcv = ((const float2*)(d_gc + (long)n * 64))[lane];
        sf[w][c]          = elu(a0 * inv + sb2[c]);
        sf[w][c + 1]      = elu(a1 * inv + sb2[c + 1]);
        sf[w][64 + c]     = gcv.x;
        sf[w][64 + c + 1] = gcv.y;
        __syncwarp();
        float acc0 = sbf[c], acc1 = sbf[c + 1];
        const float* sp = sf[w];
#pragma unroll 8
        for (int k = 0; k < 128; k++) {
            float v = sp[k];
            float2 wv = ((const float2*)&sWf[k * 64])[lane];
            acc0 += v * wv.x;
            acc1 += v * wv.y;
        }
        acc0 = fmaxf(acc0, 0.f);
        acc1 = fmaxf(acc1, 0.f);
        int b = batch[n];
        atomicAdd(d_pooled + b * 64 + c, acc0);
        atomicAdd(d_pooled + b * 64 + c + 1, acc1);
        if (lane == 0) atomicAdd(d_gcnt + b, 1.0f);
        __syncwarp();
    }
}

// ---------------- heads: pooled mean -> 2x (relu MLP 64->32->5) ----------------
__global__ void k_head(const float* __restrict__ Wc1, const float* __restrict__ bc1,
                       const float* __restrict__ Wc2, const float* __restrict__ bc2,
                       const float* __restrict__ Wp1, const float* __restrict__ bp1,
                       const float* __restrict__ Wp2, const float* __restrict__ bp2,
                       float* __restrict__ out) {
    int g = blockIdx.x, t = threadIdx.x;
    __shared__ float sp[64], sh[64];
    float cnt = fmaxf(d_gcnt[g], 1.0f);
    sp[t] = d_pooled[g * 64 + t] / cnt;
    __syncthreads();
    float hv;
    if (t < 32) {
        hv = bc1[t];
#pragma unroll 8
        for (int k = 0; k < 64; k++) hv += sp[k] * Wc1[k * 32 + t];
    } else {
        int j = t - 32;
        hv = bp1[j];
#pragma unroll 8
        for (int k = 0; k < 64; k++) hv += sp[k] * Wp1[k * 32 + j];
    }
    sh[t] = fmaxf(hv, 0.f);
    __syncthreads();
    if (t < 5) {
        float o = bc2[t];
#pragma unroll
        for (int j = 0; j < 32; j++) o += sh[j] * Wc2[j * 5 + t];
        out[g * 5 + t] = o;
    } else if (t >= 8 && t < 13) {
        int u = t - 8;
        float o = bp2[u];
#pragma unroll
        for (int j = 0; j < 32; j++) o += sh[32 + j] * Wp2[j * 5 + u];
        out[NG * 5 + g * 5 + u] = o;
    }
}

extern "C" void kernel_launch(void* const* d_in, const int* in_sizes, int n_in,
                              void* d_out, int out_size) {
    const float* x     = (const float*)d_in[0];
    const int*   ei    = (const int*)d_in[1];     // int32 (JAX x64 disabled)
    const int*   batch = (const int*)d_in[3];     // int32
    const float* W1  = (const float*)d_in[4];
    const float* as1 = (const float*)d_in[5];
    const float* ad1 = (const float*)d_in[6];
    const float* b1  = (const float*)d_in[7];
    const float* W2  = (const float*)d_in[8];
    const float* as2 = (const float*)d_in[9];
    const float* ad2 = (const float*)d_in[10];
    const float* b2  = (const float*)d_in[11];
    const float* Wg  = (const float*)d_in[12];
    const float* bg  = (const float*)d_in[13];
    const float* Wf  = (const float*)d_in[14];
    const float* bf  = (const float*)d_in[15];
    const float* Wc1 = (const float*)d_in[16];
    const float* bc1 = (const float*)d_in[17];
    const float* Wc2 = (const float*)d_in[18];
    const float* bc2 = (const float*)d_in[19];
    const float* Wp1 = (const float*)d_in[20];
    const float* bp1 = (const float*)d_in[21];
    const float* Wp2 = (const float*)d_in[22];
    const float* bp2 = (const float*)d_in[23];

    int E  = in_sizes[1] / 2;
    int te = E + NN;
    int eb = (te + 255) / 256;

    k_init<<<512, 256>>>();                                   // 0
    k_prep<<<1, 64>>>(W1, as1, ad1);                          // 1
    k_count<<<eb, 256>>>(ei, E, te);                          // 2
    k_h1x<<<(NN + 255) / 256, 256>>>(x);                      // 3 <- profiled
    k_scan1<<<SB, 1024>>>();                                  // 4
    k_scan2<<<1, 64>>>();                                     // 5
    k_scan3<<<(NN + 255) / 256, 256>>>();                     // 6
    k_fill<<<eb, 256>>>(ei, E, te);                           // 7
    k_gather1<<<(NN * 4 + 255) / 256, 256>>>(x);              // 8
    k_g1mid<<<(NN + GMN - 1) / GMN, 256>>>(W1, b1, Wg, bg);   // 9
    k_node2<<<(NN + 63) / 64, 256>>>(W2, as2, ad2);           // 10
    k_gat2<<<(NN + G2W * 8 - 1) / (G2W * 8), 256>>>(b2, bf, Wf, batch);  // 11
    k_head<<<NG, 64>>>(Wc1, bc1, Wc2, bc2, Wp1, bp1, Wp2, bp2, (float*)d_out); // 12
}

// round 10
// speedup vs baseline: 1.7801x; 1.0554x over previous
#include <cuda_runtime.h>
#include <math.h>

#define NN 50000
#define NE_MAX 800000
#define TE_MAX (NE_MAX + NN)
#define NG 128
#define SB 49   // scan blocks (49*1024 >= 50000)

// ---------------- scratch (device globals; no allocation) ----------------
__device__ __align__(16) float d_g1[NN * 256];    // elu(gat1 + b1)
__device__ __align__(16) float d_ss1[NN * 4];
__device__ __align__(16) float d_sd1[NN * 4];
__device__ __align__(16) float d_h2[NN * 64];     // g1@W2
__device__ __align__(16) float d_gc[NN * 64];     // relu(GCN + bg)
__device__ __align__(16) float d_y[NN * 56];      // per-node per-head weighted x sums
__device__ __align__(16) float d_den[NN * 4];     // softmax denominators (4 heads)
__device__ __align__(16) float d_xp[NN * 16];     // x padded to 16 floats/row
__device__ float d_z[NN * 14];                    // per-node GCN-weighted x sums
__device__ float d_ss2[NN];
__device__ float d_sd2[NN];
__device__ float d_dinv[NN];
__device__ float d_pooled[NG * 64];
__device__ float d_gcnt[NG];
__device__ float d_A1s[14 * 4];   // W1 @ as1 (per head), folded score matrices
__device__ float d_A1d[14 * 4];
// CSR by destination
__device__ int d_cnt_i[NN];
__device__ int d_off[NN + 1];
__device__ int d_csr[TE_MAX];
__device__ int d_bsum[64];

__device__ __forceinline__ float lrelu(float u) { return u > 0.f ? u : 0.2f * u; }
__device__ __forceinline__ float elu(float u)   { return u > 0.f ? u : expm1f(u); }

// ---------------- init: zero counters / accumulators; pack x to 16-wide rows ----------------
__global__ void k_init(const float* __restrict__ x) {
    int i  = blockIdx.x * blockDim.x + threadIdx.x;
    int st = gridDim.x * blockDim.x;
    for (int j = i; j < NN; j += st) d_cnt_i[j] = 0;
    for (int j = i; j < NG * 64; j += st) d_pooled[j] = 0.f;
    for (int j = i; j < NG; j += st) d_gcnt[j] = 0.f;
    for (int j = i; j < NN * 16; j += st) {
        int n = j >> 4, k = j & 15;
        d_xp[j] = (k < 14) ? x[n * 14 + k] : 0.f;
    }
}

// ---------------- prep: fold attention vectors through W1 (14x4 each) ----------------
__global__ void k_prep(const float* __restrict__ W1,
                       const float* __restrict__ as1, const float* __restrict__ ad1) {
    int t = threadIdx.x;
    if (t >= 56) return;
    int k = t >> 2, h = t & 3;
    float ss = 0.f, sd = 0.f;
#pragma unroll 8
    for (int c = 0; c < 64; c++) {
        float w = W1[k * 256 + h * 64 + c];
        ss += w * as1[h * 64 + c];
        sd += w * ad1[h * 64 + c];
    }
    d_A1s[k * 4 + h] = ss;
    d_A1d[k * 4 + h] = sd;
}

// ---------------- CSR count ----------------
__global__ void k_count(const int* __restrict__ ei, int E, int te) {
    int e = blockIdx.x * blockDim.x + threadIdx.x;
    if (e >= te) return;
    int d = (e < E) ? ei[E + e] : (e - E);
    atomicAdd(&d_cnt_i[d], 1);
}

// ---------------- GAT1 scores directly from x via folded matrices ----------------
__global__ void k_h1x(const float* __restrict__ x) {
    __shared__ float sAs[56], sAd[56];
    int t = threadIdx.x;
    if (t < 56) { sAs[t] = d_A1s[t]; sAd[t] = d_A1d[t]; }
    __syncthreads();
    int n = blockIdx.x * blockDim.x + t;
    if (n >= NN) return;
    float xv[14];
#pragma unroll
    for (int k = 0; k < 14; k++) xv[k] = x[n * 14 + k];
    float s4[4] = {0.f, 0.f, 0.f, 0.f}, p4[4] = {0.f, 0.f, 0.f, 0.f};
#pragma unroll
    for (int k = 0; k < 14; k++) {
#pragma unroll
        for (int h = 0; h < 4; h++) {
            s4[h] += xv[k] * sAs[k * 4 + h];
            p4[h] += xv[k] * sAd[k * 4 + h];
        }
    }
    ((float4*)d_ss1)[n] = make_float4(s4[0], s4[1], s4[2], s4[3]);
    ((float4*)d_sd1)[n] = make_float4(p4[0], p4[1], p4[2], p4[3]);
}

__global__ void k_scan1() {  // grid SB, 1024 thr: per-block exclusive scan + block sums
    __shared__ int sh[1024];
    int t = threadIdx.x;
    int idx = blockIdx.x * 1024 + t;
    int v = (idx < NN) ? d_cnt_i[idx] : 0;
    sh[t] = v;
    __syncthreads();
    for (int o = 1; o < 1024; o <<= 1) {
        int u = (t >= o) ? sh[t - o] : 0;
        __syncthreads();
        sh[t] += u;
        __syncthreads();
    }
    if (idx < NN) d_off[idx] = sh[t] - v;   // exclusive within block
    if (t == 1023) d_bsum[blockIdx.x] = sh[1023];
}

__global__ void k_scan2() {  // 1 block, 64 thr: exclusive scan of block sums
    __shared__ int sh[64];
    int t = threadIdx.x;
    int v = (t < SB) ? d_bsum[t] : 0;
    sh[t] = v;
    __syncthreads();
    for (int o = 1; o < 64; o <<= 1) {
        int u = (t >= o) ? sh[t - o] : 0;
        __syncthreads();
        sh[t] += u;
        __syncthreads();
    }
    if (t < SB) d_bsum[t] = sh[t] - v;
    if (t == 63) d_off[NN] = sh[63];
}

__global__ void k_scan3() {  // apply block prefix; dinv from degree (cnt_i intact here)
    int idx = blockIdx.x * blockDim.x + threadIdx.x;
    if (idx >= NN) return;
    d_off[idx] = d_off[idx] + d_bsum[idx >> 10];
    d_dinv[idx] = rsqrtf((float)d_cnt_i[idx]);
}

// fill: slot index from decrementing cnt_i (which holds degree); cnt_i ends at 0
__global__ void k_fill(const int* __restrict__ ei, int E, int te) {
    int e = blockIdx.x * blockDim.x + threadIdx.x;
    if (e >= te) return;
    int s, d;
    if (e < E) { s = ei[e]; d = ei[E + e]; } else { s = d = e - E; }
    int idx = atomicAdd(&d_cnt_i[d], -1) - 1;
    d_csr[d_off[d] + idx] = s;
}

// ---------------- gather1: ONE thread per node, all 4 heads; float4 loads of packed x ----
// y[n,h,:] = sum_s e_sh * x[s,:], den[n,h] = sum e;  z[n,:] = sum_s dinv[s]*x[s,:]
__global__ void k_gather1() {
    int n = blockIdx.x * blockDim.x + threadIdx.x;
    if (n >= NN) return;
    float4 sdv = ((const float4*)d_sd1)[n];
    int beg = d_off[n], end = d_off[n + 1];
    float y0[14] = {}, y1[14] = {}, y2[14] = {}, y3[14] = {};
    float z[14] = {};
    float den0 = 0.f, den1 = 0.f, den2 = 0.f, den3 = 0.f;
    for (int i = beg; i < end; i++) {
        int s = d_csr[i];
        float4 ssv = ((const float4*)d_ss1)[s];
        float dis = d_dinv[s];
        const float4* xr = (const float4*)(d_xp + s * 16);
        float4 xa = xr[0], xb = xr[1], xc = xr[2], xd = xr[3];
        float e0 = __expf(lrelu(ssv.x + sdv.x));
        float e1 = __expf(lrelu(ssv.y + sdv.y));
        float e2 = __expf(lrelu(ssv.z + sdv.z));
        float e3 = __expf(lrelu(ssv.w + sdv.w));
        den0 += e0; den1 += e1; den2 += e2; den3 += e3;
        float xv[14] = {xa.x, xa.y, xa.z, xa.w, xb.x, xb.y, xb.z, xb.w,
                        xc.x, xc.y, xc.z, xc.w, xd.x, xd.y};
#pragma unroll
        for (int k = 0; k < 14; k++) {
            float v = xv[k];
            y0[k] += e0 * v;
            y1[k] += e1 * v;
            y2[k] += e2 * v;
            y3[k] += e3 * v;
            z[k]  += dis * v;
        }
    }
    float* yp = d_y + n * 56;
#pragma unroll
    for (int k = 0; k < 14; k++) {
        yp[k]      = y0[k];
        yp[14 + k] = y1[k];
        yp[28 + k] = y2[k];
        yp[42 + k] = y3[k];
        d_z[n * 14 + k] = z[k];
    }
    ((float4*)d_den)[n] = make_float4(den0, den1, den2, den3);
}

// ---------------- g1mid: g1 = elu((y/den)@W1 + b1); gc = relu(dinv*(z@Wg) + bg) ----------------
#define GMN 32
__global__ void k_g1mid(const float* __restrict__ W1, const float* __restrict__ b1,
                        const float* __restrict__ Wg, const float* __restrict__ bg) {
    __shared__ float sW1[14 * 256];
    __shared__ float sWg[14 * 64];
    __shared__ float sb1[256], sbg[64];
    __shared__ float sY[4][56];
    __shared__ float sDen[4][4];
    __shared__ float sZ[4][14];
    __shared__ float sDv[4];
    int t = threadIdx.x;
    int nb = blockIdx.x * GMN;
    for (int i = t; i < 14 * 256; i += 256) sW1[i] = W1[i];
    for (int i = t; i < 14 * 64; i += 256) sWg[i] = Wg[i];
    sb1[t] = b1[t];
    if (t < 64) sbg[t] = bg[t];
    __syncthreads();
    int g = t >> 6, cc = t & 63;
#pragma unroll 1
    for (int it = 0; it < GMN / 4; it++) {
        int n = nb + it * 4 + g;
        if (n < NN) {
            if (cc < 56) sY[g][cc] = d_y[n * 56 + cc];
            else if (cc < 60) sDen[g][cc - 56] = d_den[n * 4 + (cc - 56)];
            else if (cc == 60) sDv[g] = d_dinv[n];
            if (cc < 14) sZ[g][cc] = d_z[n * 14 + cc];
        }
        __syncthreads();
        if (n < NN) {
#pragma unroll
            for (int h = 0; h < 4; h++) {
                float acc = 0.f;
#pragma unroll
                for (int k = 0; k < 14; k++) acc += sY[g][h * 14 + k] * sW1[k * 256 + h * 64 + cc];
                float inv = 1.f / (sDen[g][h] + 1e-16f);
                d_g1[(long)n * 256 + h * 64 + cc] = elu(acc * inv + sb1[h * 64 + cc]);
            }
            float accg = 0.f;
#pragma unroll
            for (int k = 0; k < 14; k++) accg += sZ[g][k] * sWg[k * 64 + cc];
            d_gc[(long)n * 64 + cc] = fmaxf(sDv[g] * accg + sbg[cc], 0.f);
        }
        __syncthreads();
    }
}

// ---------------- node pass 2: tiled GEMM h2 = g1 @ W2 + att scores ----------------
__global__ void k_node2(const float* __restrict__ W2,
                        const float* __restrict__ as2, const float* __restrict__ ad2) {
    __shared__ float sA[64][68];
    __shared__ float sB[64][68];
    __shared__ float rs[64][16];
    __shared__ float rd[64][16];
    int t = threadIdx.x;
    int nb = blockIdx.x * 64;
    int tn = t >> 4, tc = t & 15;
    float acc[4][4] = {};
#pragma unroll 1
    for (int kc = 0; kc < 4; kc++) {
#pragma unroll
        for (int j = 0; j < 4; j++) {
            int f4 = t * 4 + j;            // 0..1023
            int row = f4 >> 4;             // 0..63
            int col4 = f4 & 15;            // float4 slot
            int n = nb + row;
            float4 v = (n < NN) ? ((const float4*)(d_g1 + (long)n * 256 + kc * 64))[col4]
                                : make_float4(0.f, 0.f, 0.f, 0.f);
            ((float4*)&sA[row][0])[col4] = v;
            float4 wv = ((const float4*)(W2 + (kc * 64 + row) * 64))[col4];
            ((float4*)&sB[row][0])[col4] = wv;
        }
        __syncthreads();
#pragma unroll 4
        for (int kk = 0; kk < 64; kk++) {
            float4 bv = ((float4*)&sB[kk][0])[tc];
#pragma unroll
            for (int i = 0; i < 4; i++) {
                float av = sA[tn * 4 + i][kk];
                acc[i][0] += av * bv.x; acc[i][1] += av * bv.y;
                acc[i][2] += av * bv.z; acc[i][3] += av * bv.w;
            }
        }
        __syncthreads();
    }
    float4 av2 = ((const float4*)as2)[tc];
    float4 dv2 = ((const float4*)ad2)[tc];
#pragma unroll
    for (int i = 0; i < 4; i++) {
        int n = nb + tn * 4 + i;
        if (n < NN)
            ((float4*)(d_h2 + (long)n * 64))[tc] =
                make_float4(acc[i][0], acc[i][1], acc[i][2], acc[i][3]);
        rs[tn * 4 + i][tc] = acc[i][0] * av2.x + acc[i][1] * av2.y + acc[i][2] * av2.z + acc[i][3] * av2.w;
        rd[tn * 4 + i][tc] = acc[i][0] * dv2.x + acc[i][1] * dv2.y + acc[i][2] * dv2.z + acc[i][3] * dv2.w;
    }
    __syncthreads();
    if (t < 64) {
        int n = nb + t;
        if (n < NN) {
            float ps = 0.f, pd = 0.f;
#pragma unroll
            for (int j = 0; j < 16; j++) { ps += rs[t][j]; pd += rd[t][j]; }
            d_ss2[n] = ps;
            d_sd2[n] = pd;
        }
    }
}

// ---------------- GAT2 gather + fuse + pool: 4 nodes/warp, Wf staged once ----------------
#define G2W 4
__global__ void k_gat2(const float* __restrict__ b2, const float* __restrict__ bf,
                       const float* __restrict__ Wf,
                       const int* __restrict__ batch) {
    __shared__ float sWf[128 * 64];   // 32KB
    __shared__ float sf[8][128];
    __shared__ float sb2[64], sbf[64];
    int t = threadIdx.x, lane = t & 31, w = t >> 5;
    for (int i = t; i < 128 * 64 / 4; i += 256) ((float4*)sWf)[i] = ((const float4*)Wf)[i];
    if (t < 64) { sb2[t] = b2[t]; sbf[t] = bf[t]; }
    __syncthreads();
#pragma unroll 1
    for (int q = 0; q < G2W; q++) {
        int n = blockIdx.x * (8 * G2W) + w * G2W + q;
        if (n >= NN) continue;
        float sdv = d_sd2[n];
        int beg = d_off[n], end = d_off[n + 1];
        float a0 = 0.f, a1 = 0.f, den = 0.f;
        int i = beg;
        for (; i + 2 <= end; i += 2) {
            int s0 = d_csr[i], s1 = d_csr[i + 1];
            float l0 = d_ss2[s0], l1 = d_ss2[s1];
            float2 h0 = ((const float2*)(d_h2 + (long)s0 * 64))[lane];
            float2 h1v = ((const float2*)(d_h2 + (long)s1 * 64))[lane];
            float e0 = __expf(lrelu(l0 + sdv));
            float e1 = __expf(lrelu(l1 + sdv));
            den += e0 + e1;
            a0 += h0.x * e0 + h1v.x * e1;
            a1 += h0.y * e0 + h1v.y * e1;
        }
        if (i < end) {
            int s = d_csr[i];
            float e = __expf(lrelu(d_ss2[s] + sdv));
            den += e;
            float2 h = ((const float2*)(d_h2 + (long)s * 64))[lane];
            a0 += h.x * e; a1 += h.y * e;
        }
        float inv = 1.f / (den + 1e-16f);
        int c = 2 * lane;
        float2 gcv = ((const float2*)(d_gc + (long)n * 64))[lane];
        sf[w][c]          = elu(a0 * inv + sb2[c]);
        sf[w][c + 1]      = elu(a1 * inv + sb2[c + 1]);
        sf[w][64 + c]     = gcv.x;
        sf[w][64 + c + 1] = gcv.y;
        __syncwarp();
        float acc0 = sbf[c], acc1 = sbf[c + 1];
        const float* sp = sf[w];
#pragma unroll 8
        for (int k = 0; k < 128; k++) {
            float v = sp[k];
            float2 wv = ((const float2*)&sWf[k * 64])[lane];
            acc0 += v * wv.x;
            acc1 += v * wv.y;
        }
        acc0 = fmaxf(acc0, 0.f);
        acc1 = fmaxf(acc1, 0.f);
        int b = batch[n];
        atomicAdd(d_pooled + b * 64 + c, acc0);
        atomicAdd(d_pooled + b * 64 + c + 1, acc1);
        if (lane == 0) atomicAdd(d_gcnt + b, 1.0f);
        __syncwarp();
    }
}

// ---------------- heads: pooled mean -> 2x (relu MLP 64->32->5) ----------------
__global__ void k_head(const float* __restrict__ Wc1, const float* __restrict__ bc1,
                       const float* __restrict__ Wc2, const float* __restrict__ bc2,
                       const float* __restrict__ Wp1, const float* __restrict__ bp1,
                       const float* __restrict__ Wp2, const float* __restrict__ bp2,
                       float* __restrict__ out) {
    int g = blockIdx.x, t = threadIdx.x;
    __shared__ float sp[64], sh[64];
    float cnt = fmaxf(d_gcnt[g], 1.0f);
    sp[t] = d_pooled[g * 64 + t] / cnt;
    __syncthreads();
    float hv;
    if (t < 32) {
        hv = bc1[t];
#pragma unroll 8
        for (int k = 0; k < 64; k++) hv += sp[k] * Wc1[k * 32 + t];
    } else {
        int j = t - 32;
        hv = bp1[j];
#pragma unroll 8
        for (int k = 0; k < 64; k++) hv += sp[k] * Wp1[k * 32 + j];
    }
    sh[t] = fmaxf(hv, 0.f);
    __syncthreads();
    if (t < 5) {
        float o = bc2[t];
#pragma unroll
        for (int j = 0; j < 32; j++) o += sh[j] * Wc2[j * 5 + t];
        out[g * 5 + t] = o;
    } else if (t >= 8 && t < 13) {
        int u = t - 8;
        float o = bp2[u];
#pragma unroll
        for (int j = 0; j < 32; j++) o += sh[32 + j] * Wp2[j * 5 + u];
        out[NG * 5 + g * 5 + u] = o;
    }
}

extern "C" void kernel_launch(void* const* d_in, const int* in_sizes, int n_in,
                              void* d_out, int out_size) {
    const float* x     = (const float*)d_in[0];
    const int*   ei    = (const int*)d_in[1];     // int32 (JAX x64 disabled)
    const int*   batch = (const int*)d_in[3];     // int32
    const float* W1  = (const float*)d_in[4];
    const float* as1 = (const float*)d_in[5];
    const float* ad1 = (const float*)d_in[6];
    const float* b1  = (const float*)d_in[7];
    const float* W2  = (const float*)d_in[8];
    const float* as2 = (const float*)d_in[9];
    const float* ad2 = (const float*)d_in[10];
    const float* b2  = (const float*)d_in[11];
    const float* Wg  = (const float*)d_in[12];
    const float* bg  = (const float*)d_in[13];
    const float* Wf  = (const float*)d_in[14];
    const float* bf  = (const float*)d_in[15];
    const float* Wc1 = (const float*)d_in[16];
    const float* bc1 = (const float*)d_in[17];
    const float* Wc2 = (const float*)d_in[18];
    const float* bc2 = (const float*)d_in[19];
    const float* Wp1 = (const float*)d_in[20];
    const float* bp1 = (const float*)d_in[21];
    const float* Wp2 = (const float*)d_in[22];
    const float* bp2 = (const float*)d_in[23];

    int E  = in_sizes[1] / 2;
    int te = E + NN;
    int eb = (te + 255) / 256;

    k_init<<<512, 256>>>(x);                                  // 0
    k_prep<<<1, 64>>>(W1, as1, ad1);                          // 1
    k_count<<<eb, 256>>>(ei, E, te);                          // 2
    k_h1x<<<(NN + 255) / 256, 256>>>(x);                      // 3 <- profiled
    k_scan1<<<SB, 1024>>>();                                  // 4
    k_scan2<<<1, 64>>>();                                     // 5
    k_scan3<<<(NN + 255) / 256, 256>>>();                     // 6
    k_fill<<<eb, 256>>>(ei, E, te);                           // 7
    k_gather1<<<(NN + 127) / 128, 128>>>();                   // 8
    k_g1mid<<<(NN + GMN - 1) / GMN, 256>>>(W1, b1, Wg, bg);   // 9
    k_node2<<<(NN + 63) / 64, 256>>>(W2, as2, ad2);           // 10
    k_gat2<<<(NN + G2W * 8 - 1) / (G2W * 8), 256>>>(b2, bf, Wf, batch);  // 11
    k_head<<<NG, 64>>>(Wc1, bc1, Wc2, bc2, Wp1, bp1, Wp2, bp2, (float*)d_out); // 12
}

// round 11
// speedup vs baseline: 1.9132x; 1.0748x over previous
#include <cuda_runtime.h>
#include <math.h>

#define NN 50000
#define NE_MAX 800000
#define TE_MAX (NE_MAX + NN)
#define NG 128
#define SB 49   // scan blocks (49*1024 >= 50000)

// ---------------- scratch (device globals; no allocation) ----------------
__device__ __align__(16) float d_ss1[NN * 4];
__device__ __align__(16) float d_sd1[NN * 4];
__device__ __align__(16) float d_h2[NN * 64];     // h2 = g1@W2 (g1 never materialized)
__device__ __align__(16) float d_gc[NN * 64];     // relu(GCN + bg)
__device__ __align__(16) float d_y[NN * 56];      // per-node per-head weighted x sums
__device__ __align__(16) float d_den[NN * 4];     // softmax denominators (4 heads)
__device__ __align__(16) float d_xp[NN * 16];     // x padded to 16 floats/row
__device__ float d_z[NN * 14];                    // per-node GCN-weighted x sums
__device__ float d_ss2[NN];
__device__ float d_sd2[NN];
__device__ float d_dinv[NN];
__device__ float d_pooled[NG * 64];
__device__ float d_gcnt[NG];
__device__ float d_A1s[14 * 4];   // W1 @ as1 (per head), folded score matrices
__device__ float d_A1d[14 * 4];
// CSR by destination
__device__ int d_cnt_i[NN];
__device__ int d_off[NN + 1];
__device__ int d_csr[TE_MAX];
__device__ int d_bsum[64];

__device__ __forceinline__ float lrelu(float u) { return u > 0.f ? u : 0.2f * u; }
__device__ __forceinline__ float elu(float u)   { return u > 0.f ? u : expm1f(u); }

// ---------------- init: zero counters / accumulators; pack x to 16-wide rows ----------------
__global__ void k_init(const float* __restrict__ x) {
    int i  = blockIdx.x * blockDim.x + threadIdx.x;
    int st = gridDim.x * blockDim.x;
    for (int j = i; j < NN; j += st) d_cnt_i[j] = 0;
    for (int j = i; j < NG * 64; j += st) d_pooled[j] = 0.f;
    for (int j = i; j < NG; j += st) d_gcnt[j] = 0.f;
    for (int j = i; j < NN * 16; j += st) {
        int n = j >> 4, k = j & 15;
        d_xp[j] = (k < 14) ? x[n * 14 + k] : 0.f;
    }
}

// ---------------- prep: fold attention vectors through W1 (14x4 each) ----------------
__global__ void k_prep(const float* __restrict__ W1,
                       const float* __restrict__ as1, const float* __restrict__ ad1) {
    int t = threadIdx.x;
    if (t >= 56) return;
    int k = t >> 2, h = t & 3;
    float ss = 0.f, sd = 0.f;
#pragma unroll 8
    for (int c = 0; c < 64; c++) {
        float w = W1[k * 256 + h * 64 + c];
        ss += w * as1[h * 64 + c];
        sd += w * ad1[h * 64 + c];
    }
    d_A1s[k * 4 + h] = ss;
    d_A1d[k * 4 + h] = sd;
}

// ---------------- CSR count ----------------
__global__ void k_count(const int* __restrict__ ei, int E, int te) {
    int e = blockIdx.x * blockDim.x + threadIdx.x;
    if (e >= te) return;
    int d = (e < E) ? ei[E + e] : (e - E);
    atomicAdd(&d_cnt_i[d], 1);
}

// ---------------- GAT1 scores directly from x via folded matrices ----------------
__global__ void k_h1x(const float* __restrict__ x) {
    __shared__ float sAs[56], sAd[56];
    int t = threadIdx.x;
    if (t < 56) { sAs[t] = d_A1s[t]; sAd[t] = d_A1d[t]; }
    __syncthreads();
    int n = blockIdx.x * blockDim.x + t;
    if (n >= NN) return;
    float xv[14];
#pragma unroll
    for (int k = 0; k < 14; k++) xv[k] = x[n * 14 + k];
    float s4[4] = {0.f, 0.f, 0.f, 0.f}, p4[4] = {0.f, 0.f, 0.f, 0.f};
#pragma unroll
    for (int k = 0; k < 14; k++) {
#pragma unroll
        for (int h = 0; h < 4; h++) {
            s4[h] += xv[k] * sAs[k * 4 + h];
            p4[h] += xv[k] * sAd[k * 4 + h];
        }
    }
    ((float4*)d_ss1)[n] = make_float4(s4[0], s4[1], s4[2], s4[3]);
    ((float4*)d_sd1)[n] = make_float4(p4[0], p4[1], p4[2], p4[3]);
}

__global__ void k_scan1() {  // grid SB, 1024 thr: per-block exclusive scan + block sums
    __shared__ int sh[1024];
    int t = threadIdx.x;
    int idx = blockIdx.x * 1024 + t;
    int v = (idx < NN) ? d_cnt_i[idx] : 0;
    sh[t] = v;
    __syncthreads();
    for (int o = 1; o < 1024; o <<= 1) {
        int u = (t >= o) ? sh[t - o] : 0;
        __syncthreads();
        sh[t] += u;
        __syncthreads();
    }
    if (idx < NN) d_off[idx] = sh[t] - v;   // exclusive within block
    if (t == 1023) d_bsum[blockIdx.x] = sh[1023];
}

__global__ void k_scan2() {  // 1 block, 64 thr: exclusive scan of block sums
    __shared__ int sh[64];
    int t = threadIdx.x;
    int v = (t < SB) ? d_bsum[t] : 0;
    sh[t] = v;
    __syncthreads();
    for (int o = 1; o < 64; o <<= 1) {
        int u = (t >= o) ? sh[t - o] : 0;
        __syncthreads();
        sh[t] += u;
        __syncthreads();
    }
    if (t < SB) d_bsum[t] = sh[t] - v;
    if (t == 63) d_off[NN] = sh[63];
}

__global__ void k_scan3() {  // apply block prefix; dinv from degree (cnt_i intact here)
    int idx = blockIdx.x * blockDim.x + threadIdx.x;
    if (idx >= NN) return;
    d_off[idx] = d_off[idx] + d_bsum[idx >> 10];
    d_dinv[idx] = rsqrtf((float)d_cnt_i[idx]);
}

// fill: slot index from decrementing cnt_i (which holds degree); cnt_i ends at 0
__global__ void k_fill(const int* __restrict__ ei, int E, int te) {
    int e = blockIdx.x * blockDim.x + threadIdx.x;
    if (e >= te) return;
    int s, d;
    if (e < E) { s = ei[e]; d = ei[E + e]; } else { s = d = e - E; }
    int idx = atomicAdd(&d_cnt_i[d], -1) - 1;
    d_csr[d_off[d] + idx] = s;
}

// ---------------- gather1: ONE thread per node, all 4 heads; float4 loads of packed x ----
__global__ void k_gather1() {
    int n = blockIdx.x * blockDim.x + threadIdx.x;
    if (n >= NN) return;
    float4 sdv = ((const float4*)d_sd1)[n];
    int beg = d_off[n], end = d_off[n + 1];
    float y0[14] = {}, y1[14] = {}, y2[14] = {}, y3[14] = {};
    float z[14] = {};
    float den0 = 0.f, den1 = 0.f, den2 = 0.f, den3 = 0.f;
    for (int i = beg; i < end; i++) {
        int s = d_csr[i];
        float4 ssv = ((const float4*)d_ss1)[s];
        float dis = d_dinv[s];
        const float4* xr = (const float4*)(d_xp + s * 16);
        float4 xa = xr[0], xb = xr[1], xc = xr[2], xd = xr[3];
        float e0 = __expf(lrelu(ssv.x + sdv.x));
        float e1 = __expf(lrelu(ssv.y + sdv.y));
        float e2 = __expf(lrelu(ssv.z + sdv.z));
        float e3 = __expf(lrelu(ssv.w + sdv.w));
        den0 += e0; den1 += e1; den2 += e2; den3 += e3;
        float xv[14] = {xa.x, xa.y, xa.z, xa.w, xb.x, xb.y, xb.z, xb.w,
                        xc.x, xc.y, xc.z, xc.w, xd.x, xd.y};
#pragma unroll
        for (int k = 0; k < 14; k++) {
            float v = xv[k];
            y0[k] += e0 * v;
            y1[k] += e1 * v;
            y2[k] += e2 * v;
            y3[k] += e3 * v;
            z[k]  += dis * v;
        }
    }
    float* yp = d_y + n * 56;
#pragma unroll
    for (int k = 0; k < 14; k++) {
        yp[k]      = y0[k];
        yp[14 + k] = y1[k];
        yp[28 + k] = y2[k];
        yp[42 + k] = y3[k];
        d_z[n * 14 + k] = z[k];
    }
    ((float4*)d_den)[n] = make_float4(den0, den1, den2, den3);
}

// ---------------- fuse2: h2 = elu((y/den)@W1 + b1) @ W2, g1 never materialized ----------------
// Per 64-node block: for each 64-wide chunk (= head), build the g1 tile in smem
// from y/den/W1/b1, then accumulate the tiled GEMM against the W2 chunk.
__global__ void k_fuse2(const float* __restrict__ W1, const float* __restrict__ b1,
                        const float* __restrict__ W2,
                        const float* __restrict__ as2, const float* __restrict__ ad2) {
    __shared__ float sA[64][68];
    __shared__ float sB[64][68];
    __shared__ float sW1c[14][64];
    __shared__ float sYc[64][16];
    __shared__ float sden[64];
    __shared__ float sb1c[64];
    int t = threadIdx.x;
    int nb = blockIdx.x * 64;
    int tn = t >> 4, tc = t & 15;
    float acc[4][4] = {};
#pragma unroll 1
    for (int kc = 0; kc < 4; kc++) {
        // stage W2 chunk
#pragma unroll
        for (int j = 0; j < 4; j++) {
            int f4 = t * 4 + j;
            int row = f4 >> 4, col4 = f4 & 15;
            float4 wv = ((const float4*)(W2 + (kc * 64 + row) * 64))[col4];
            ((float4*)&sB[row][0])[col4] = wv;
        }
        // stage W1 chunk (cols kc*64..kc*64+63)
        for (int i = t; i < 14 * 64; i += 256) {
            int k = i >> 6, c = i & 63;
            sW1c[k][c] = W1[k * 256 + kc * 64 + c];
        }
        // stage y chunk for this head
        for (int i = t; i < 64 * 14; i += 256) {
            int row = i / 14, k = i - row * 14;
            int n = nb + row;
            sYc[row][k] = (n < NN) ? d_y[n * 56 + kc * 14 + k] : 0.f;
        }
        if (t < 64) {
            int n = nb + t;
            sden[t] = (n < NN) ? d_den[n * 4 + kc] : 1.f;
            sb1c[t] = b1[kc * 64 + t];
        }
        __syncthreads();
        // build g1 tile in sA: each thread 4x4 values
#pragma unroll
        for (int i = 0; i < 4; i++) {
            int row = tn * 4 + i;
            float inv = 1.f / (sden[row] + 1e-16f);
#pragma unroll
            for (int j = 0; j < 4; j++) {
                int col = tc * 4 + j;
                float a2 = 0.f;
#pragma unroll
                for (int k = 0; k < 14; k++) a2 += sYc[row][k] * sW1c[k][col];
                sA[row][col] = elu(a2 * inv + sb1c[col]);
            }
        }
        __syncthreads();
        // GEMM chunk
#pragma unroll 4
        for (int kk = 0; kk < 64; kk++) {
            float4 bv = ((float4*)&sB[kk][0])[tc];
#pragma unroll
            for (int i = 0; i < 4; i++) {
                float av = sA[tn * 4 + i][kk];
                acc[i][0] += av * bv.x; acc[i][1] += av * bv.y;
                acc[i][2] += av * bv.z; acc[i][3] += av * bv.w;
            }
        }
        __syncthreads();
    }
    // epilogue: write h2, attention scores via width-16 shuffle reduction
    float4 av2 = ((const float4*)as2)[tc];
    float4 dv2 = ((const float4*)ad2)[tc];
#pragma unroll
    for (int i = 0; i < 4; i++) {
        int n = nb + tn * 4 + i;
        float ps = acc[i][0] * av2.x + acc[i][1] * av2.y + acc[i][2] * av2.z + acc[i][3] * av2.w;
        float pd = acc[i][0] * dv2.x + acc[i][1] * dv2.y + acc[i][2] * dv2.z + acc[i][3] * dv2.w;
#pragma unroll
        for (int o = 8; o > 0; o >>= 1) {
            ps += __shfl_down_sync(0xFFFFFFFFu, ps, o, 16);
            pd += __shfl_down_sync(0xFFFFFFFFu, pd, o, 16);
        }
        if (n < NN) {
            ((float4*)(d_h2 + (long)n * 64))[tc] =
                make_float4(acc[i][0], acc[i][1], acc[i][2], acc[i][3]);
            if (tc == 0) { d_ss2[n] = ps; d_sd2[n] = pd; }
        }
    }
}

// ---------------- gc: relu(dinv * (z@Wg) + bg); 16 nodes per block ----------------
__global__ void k_gc(const float* __restrict__ Wg, const float* __restrict__ bg) {
    __shared__ float sWg[14][64];
    __shared__ float sbg[64];
    __shared__ float sZ[16][16];
    __shared__ float sDv[16];
    int t = threadIdx.x;
    int nb = blockIdx.x * 16;
    for (int i = t; i < 14 * 64; i += 256) sWg[i >> 6][i & 63] = Wg[i];
    if (t < 64) sbg[t] = bg[t];
    if (t < 16 * 14) {
        int q = t / 14, k = t - q * 14;
        int n = nb + q;
        sZ[q][k] = (n < NN) ? d_z[n * 14 + k] : 0.f;
    }
    if (t >= 224 && t < 240) {
        int q = t - 224;
        sDv[q] = (nb + q < NN) ? d_dinv[nb + q] : 0.f;
    }
    __syncthreads();
    int g = t >> 6, c = t & 63;
#pragma unroll 1
    for (int it = 0; it < 4; it++) {
        int q = it * 4 + g;
        int n = nb + q;
        if (n < NN) {
            float a = 0.f;
#pragma unroll
            for (int k = 0; k < 14; k++) a += sZ[q][k] * sWg[k][c];
            d_gc[(long)n * 64 + c] = fmaxf(sDv[q] * a + sbg[c], 0.f);
        }
    }
}

// ---------------- GAT2 gather + fuse + pool: 4 nodes/warp, Wf staged once ----------------
#define G2W 4
__global__ void k_gat2(const float* __restrict__ b2, const float* __restrict__ bf,
                       const float* __restrict__ Wf,
                       const int* __restrict__ batch) {
    __shared__ float sWf[128 * 64];   // 32KB
    __shared__ float sf[8][128];
    __shared__ float sb2[64], sbf[64];
    int t = threadIdx.x, lane = t & 31, w = t >> 5;
    for (int i = t; i < 128 * 64 / 4; i += 256) ((float4*)sWf)[i] = ((const float4*)Wf)[i];
    if (t < 64) { sb2[t] = b2[t]; sbf[t] = bf[t]; }
    __syncthreads();
#pragma unroll 1
    for (int q = 0; q < G2W; q++) {
        int n = blockIdx.x * (8 * G2W) + w * G2W + q;
        if (n >= NN) continue;
        float sdv = d_sd2[n];
        int beg = d_off[n], end = d_off[n + 1];
        float a0 = 0.f, a1 = 0.f, den = 0.f;
        int i = beg;
        for (; i + 2 <= end; i += 2) {
            int s0 = d_csr[i], s1 = d_csr[i + 1];
            float l0 = d_ss2[s0], l1 = d_ss2[s1];
            float2 h0 = ((const float2*)(d_h2 + (long)s0 * 64))[lane];
            float2 h1v = ((const float2*)(d_h2 + (long)s1 * 64))[lane];
            float e0 = __expf(lrelu(l0 + sdv));
            float e1 = __expf(lrelu(l1 + sdv));
            den += e0 + e1;
            a0 += h0.x * e0 + h1v.x * e1;
            a1 += h0.y * e0 + h1v.y * e1;
        }
        if (i < end) {
            int s = d_csr[i];
            float e = __expf(lrelu(d_ss2[s] + sdv));
            den += e;
            float2 h = ((const float2*)(d_h2 + (long)s * 64))[lane];
            a0 += h.x * e; a1 += h.y * e;
        }
        float inv = 1.f / (den + 1e-16f);
        int c = 2 * lane;
        float2 gcv = ((const float2*)(d_gc + (long)n * 64))[lane];
        sf[w][c]          = elu(a0 * inv + sb2[c]);
        sf[w][c + 1]      = elu(a1 * inv + sb2[c + 1]);
        sf[w][64 + c]     = gcv.x;
        sf[w][64 + c + 1] = gcv.y;
        __syncwarp();
        float acc0 = sbf[c], acc1 = sbf[c + 1];
        const float* sp = sf[w];
#pragma unroll 8
        for (int k = 0; k < 128; k++) {
            float v = sp[k];
            float2 wv = ((const float2*)&sWf[k * 64])[lane];
            acc0 += v * wv.x;
            acc1 += v * wv.y;
        }
        acc0 = fmaxf(acc0, 0.f);
        acc1 = fmaxf(acc1, 0.f);
        int b = batch[n];
        atomicAdd(d_pooled + b * 64 + c, acc0);
        atomicAdd(d_pooled + b * 64 + c + 1, acc1);
        if (lane == 0) atomicAdd(d_gcnt + b, 1.0f);
        __syncwarp();
    }
}

// ---------------- heads: pooled mean -> 2x (relu MLP 64->32->5) ----------------
__global__ void k_head(const float* __restrict__ Wc1, const float* __restrict__ bc1,
                       const float* __restrict__ Wc2, const float* __restrict__ bc2,
                       const float* __restrict__ Wp1, const float* __restrict__ bp1,
                       const float* __restrict__ Wp2, const float* __restrict__ bp2,
                       float* __restrict__ out) {
    int g = blockIdx.x, t = threadIdx.x;
    __shared__ float sp[64], sh[64];
    float cnt = fmaxf(d_gcnt[g], 1.0f);
    sp[t] = d_pooled[g * 64 + t] / cnt;
    __syncthreads();
    float hv;
    if (t < 32) {
        hv = bc1[t];
#pragma unroll 8
        for (int k = 0; k < 64; k++) hv += sp[k] * Wc1[k * 32 + t];
    } else {
        int j = t - 32;
        hv = bp1[j];
#pragma unroll 8
        for (int k = 0; k < 64; k++) hv += sp[k] * Wp1[k * 32 + j];
    }
    sh[t] = fmaxf(hv, 0.f);
    __syncthreads();
    if (t < 5) {
        float o = bc2[t];
#pragma unroll
        for (int j = 0; j < 32; j++) o += sh[j] * Wc2[j * 5 + t];
        out[g * 5 + t] = o;
    } else if (t >= 8 && t < 13) {
        int u = t - 8;
        float o = bp2[u];
#pragma unroll
        for (int j = 0; j < 32; j++) o += sh[32 + j] * Wp2[j * 5 + u];
        out[NG * 5 + g * 5 + u] = o;
    }
}

extern "C" void kernel_launch(void* const* d_in, const int* in_sizes, int n_in,
                              void* d_out, int out_size) {
    const float* x     = (const float*)d_in[0];
    const int*   ei    = (const int*)d_in[1];     // int32 (JAX x64 disabled)
    const int*   batch = (const int*)d_in[3];     // int32
    const float* W1  = (const float*)d_in[4];
    const float* as1 = (const float*)d_in[5];
    const float* ad1 = (const float*)d_in[6];
    const float* b1  = (const float*)d_in[7];
    const float* W2  = (const float*)d_in[8];
    const float* as2 = (const float*)d_in[9];
    const float* ad2 = (const float*)d_in[10];
    const float* b2  = (const float*)d_in[11];
    const float* Wg  = (const float*)d_in[12];
    const float* bg  = (const float*)d_in[13];
    const float* Wf  = (const float*)d_in[14];
    const float* bf  = (const float*)d_in[15];
    const float* Wc1 = (const float*)d_in[16];
    const float* bc1 = (const float*)d_in[17];
    const float* Wc2 = (const float*)d_in[18];
    const float* bc2 = (const float*)d_in[19];
    const float* Wp1 = (const float*)d_in[20];
    const float* bp1 = (const float*)d_in[21];
    const float* Wp2 = (const float*)d_in[22];
    const float* bp2 = (const float*)d_in[23];

    int E  = in_sizes[1] / 2;
    int te = E + NN;
    int eb = (te + 255) / 256;

    k_init<<<512, 256>>>(x);                                  // 0
    k_prep<<<1, 64>>>(W1, as1, ad1);                          // 1
    k_count<<<eb, 256>>>(ei, E, te);                          // 2
    k_h1x<<<(NN + 255) / 256, 256>>>(x);                      // 3 <- profiled
    k_scan1<<<SB, 1024>>>();                                  // 4
    k_scan2<<<1, 64>>>();                                     // 5
    k_scan3<<<(NN + 255) / 256, 256>>>();                     // 6
    k_fill<<<eb, 256>>>(ei, E, te);                           // 7
    k_gather1<<<(NN + 127) / 128, 128>>>();                   // 8
    k_fuse2<<<(NN + 63) / 64, 256>>>(W1, b1, W2, as2, ad2);   // 9
    k_gc<<<(NN + 15) / 16, 256>>>(Wg, bg);                    // 10
    k_gat2<<<(NN + G2W * 8 - 1) / (G2W * 8), 256>>>(b2, bf, Wf, batch);  // 11
    k_head<<<NG, 64>>>(Wc1, bc1, Wc2, bc2, Wp1, bp1, Wp2, bp2, (float*)d_out); // 12
}

// round 12
// speedup vs baseline: 1.9134x; 1.0001x over previous
#include <cuda_runtime.h>
#include <math.h>

#define NN 50000
#define NE_MAX 800000
#define TE_MAX (NE_MAX + NN)
#define NG 128
#define SB 49   // scan blocks (49*1024 >= 50000)

// ---------------- scratch (device globals; no allocation) ----------------
__device__ __align__(16) float d_ss1[NN * 4];
__device__ __align__(16) float d_sd1[NN * 4];
__device__ __align__(16) float d_h2[NN * 64];     // h2 = g1@W2 (g1 never materialized)
__device__ __align__(16) float d_gc[NN * 64];     // relu(GCN + bg)
__device__ __align__(16) float d_y[NN * 56];      // per-node per-head weighted x sums
__device__ __align__(16) float d_den[NN * 4];     // softmax denominators (4 heads)
__device__ __align__(16) float d_xp[NN * 16];     // x padded: [x(14), dinv, 0]
__device__ float d_ss2[NN];
__device__ float d_sd2[NN];
__device__ float d_pooled[NG * 64];
__device__ float d_gcnt[NG];
// CSR by destination
__device__ int d_cnt_i[NN];
__device__ int d_off[NN + 1];
__device__ int d_csr[TE_MAX];
__device__ int d_bsum[64];

__device__ __forceinline__ float lrelu(float u) { return u > 0.f ? u : 0.2f * u; }
__device__ __forceinline__ float elu(float u)   { return u > 0.f ? u : expm1f(u); }

// ---------------- init: zero accumulators; pack x; GAT1 scores via folded A1 ----------------
__global__ void k_init(const float* __restrict__ x, const float* __restrict__ W1,
                       const float* __restrict__ as1, const float* __restrict__ ad1) {
    __shared__ float sAs[56], sAd[56];
    int t = threadIdx.x;
    if (t < 56) {                       // per-block redundant fold: A1 = W1 @ a1 (14x4)
        int k = t >> 2, h = t & 3;
        float ss = 0.f, sd = 0.f;
#pragma unroll 8
        for (int c = 0; c < 64; c++) {
            float w = W1[k * 256 + h * 64 + c];
            ss += w * as1[h * 64 + c];
            sd += w * ad1[h * 64 + c];
        }
        sAs[t] = ss;
        sAd[t] = sd;
    }
    __syncthreads();
    int i  = blockIdx.x * blockDim.x + t;
    int st = gridDim.x * blockDim.x;
    for (int j = i; j < NN; j += st) d_cnt_i[j] = 0;
    for (int j = i; j < NG * 64; j += st) d_pooled[j] = 0.f;
    for (int j = i; j < NG; j += st) d_gcnt[j] = 0.f;
    for (int n = i; n < NN; n += st) {
        float xv[14];
#pragma unroll
        for (int k = 0; k < 14; k++) xv[k] = x[n * 14 + k];
        float s4[4] = {}, p4[4] = {};
#pragma unroll
        for (int k = 0; k < 14; k++) {
#pragma unroll
            for (int h = 0; h < 4; h++) {
                s4[h] += xv[k] * sAs[k * 4 + h];
                p4[h] += xv[k] * sAd[k * 4 + h];
            }
        }
        ((float4*)d_ss1)[n] = make_float4(s4[0], s4[1], s4[2], s4[3]);
        ((float4*)d_sd1)[n] = make_float4(p4[0], p4[1], p4[2], p4[3]);
        float4* xr = (float4*)(d_xp + n * 16);
        xr[0] = make_float4(xv[0], xv[1], xv[2], xv[3]);
        xr[1] = make_float4(xv[4], xv[5], xv[6], xv[7]);
        xr[2] = make_float4(xv[8], xv[9], xv[10], xv[11]);
        xr[3] = make_float4(xv[12], xv[13], 0.f, 0.f);   // slot 14 = dinv (set by scan3)
    }
}

// ---------------- CSR count ----------------
__global__ void k_count(const int* __restrict__ ei, int E, int te) {
    int e = blockIdx.x * blockDim.x + threadIdx.x;
    if (e >= te) return;
    int d = (e < E) ? ei[E + e] : (e - E);
    atomicAdd(&d_cnt_i[d], 1);
}

__global__ void k_scan1() {  // grid SB, 1024 thr: per-block exclusive scan + block sums
    __shared__ int sh[1024];
    int t = threadIdx.x;
    int idx = blockIdx.x * 1024 + t;
    int v = (idx < NN) ? d_cnt_i[idx] : 0;
    sh[t] = v;
    __syncthreads();
    for (int o = 1; o < 1024; o <<= 1) {
        int u = (t >= o) ? sh[t - o] : 0;
        __syncthreads();
        sh[t] += u;
        __syncthreads();
    }
    if (idx < NN) d_off[idx] = sh[t] - v;   // exclusive within block
    if (t == 1023) d_bsum[blockIdx.x] = sh[1023];
}

__global__ void k_scan2() {  // 1 block, 64 thr: exclusive scan of block sums
    __shared__ int sh[64];
    int t = threadIdx.x;
    int v = (t < SB) ? d_bsum[t] : 0;
    sh[t] = v;
    __syncthreads();
    for (int o = 1; o < 64; o <<= 1) {
        int u = (t >= o) ? sh[t - o] : 0;
        __syncthreads();
        sh[t] += u;
        __syncthreads();
    }
    if (t < SB) d_bsum[t] = sh[t] - v;
    if (t == 63) d_off[NN] = sh[63];
}

__global__ void k_scan3() {  // apply block prefix; dinv -> xp slot 14
    int idx = blockIdx.x * blockDim.x + threadIdx.x;
    if (idx >= NN) return;
    d_off[idx] = d_off[idx] + d_bsum[idx >> 10];
    d_xp[idx * 16 + 14] = rsqrtf((float)d_cnt_i[idx]);
}

// fill: slot index from decrementing cnt_i (which holds degree); cnt_i ends at 0
__global__ void k_fill(const int* __restrict__ ei, int E, int te) {
    int e = blockIdx.x * blockDim.x + threadIdx.x;
    if (e >= te) return;
    int s, d;
    if (e < E) { s = ei[e]; d = ei[E + e]; } else { s = d = e - E; }
    int idx = atomicAdd(&d_cnt_i[d], -1) - 1;
    d_csr[d_off[d] + idx] = s;
}

// ---------------- gather1: TWO threads per node; fused gc epilogue ----------------
// y[n,h,:] = sum_s e_sh * x[s,:]; den[n,h] = sum e; z = sum dinv[s]*x[s,:];
// gc[n,:] = relu(dinv[n] * (z @ Wg) + bg)
__global__ void k_gather1(const float* __restrict__ Wg, const float* __restrict__ bg) {
    __shared__ float sWg[14][64];
    __shared__ float sbg[64];
    int t = threadIdx.x;
    for (int i = t; i < 14 * 64; i += 128) sWg[i >> 6][i & 63] = Wg[i];
    if (t < 64) sbg[t] = bg[t];
    __syncthreads();
    int gid = blockIdx.x * blockDim.x + t;
    int n = gid >> 1, par = gid & 1;
    bool valid = n < NN;
    if (n >= NN) n = NN - 1;           // clamp: keep lanes converged for shuffles
    float4 sdv = ((const float4*)d_sd1)[n];
    int beg = d_off[n], end = d_off[n + 1];
    float y0[14] = {}, y1[14] = {}, y2[14] = {}, y3[14] = {};
    float z[14] = {};
    float den0 = 0.f, den1 = 0.f, den2 = 0.f, den3 = 0.f;
    for (int i = beg + par; i < end; i += 2) {
        int s = d_csr[i];
        float4 ssv = ((const float4*)d_ss1)[s];
        const float4* xr = (const float4*)(d_xp + s * 16);
        float4 xa = xr[0], xb = xr[1], xc = xr[2], xd = xr[3];
        float dis = xd.z;              // dinv[s] packed at slot 14
        float e0 = __expf(lrelu(ssv.x + sdv.x));
        float e1 = __expf(lrelu(ssv.y + sdv.y));
        float e2 = __expf(lrelu(ssv.z + sdv.z));
        float e3 = __expf(lrelu(ssv.w + sdv.w));
        den0 += e0; den1 += e1; den2 += e2; den3 += e3;
        float xv[14] = {xa.x, xa.y, xa.z, xa.w, xb.x, xb.y, xb.z, xb.w,
                        xc.x, xc.y, xc.z, xc.w, xd.x, xd.y};
#pragma unroll
        for (int k = 0; k < 14; k++) {
            float v = xv[k];
            y0[k] += e0 * v;
            y1[k] += e1 * v;
            y2[k] += e2 * v;
            y3[k] += e3 * v;
            z[k]  += dis * v;
        }
    }
    // combine pair (lanes differ in bit0 of gid -> adjacent lanes)
#pragma unroll
    for (int k = 0; k < 14; k++) {
        y0[k] += __shfl_xor_sync(0xFFFFFFFFu, y0[k], 1);
        y1[k] += __shfl_xor_sync(0xFFFFFFFFu, y1[k], 1);
        y2[k] += __shfl_xor_sync(0xFFFFFFFFu, y2[k], 1);
        y3[k] += __shfl_xor_sync(0xFFFFFFFFu, y3[k], 1);
        z[k]  += __shfl_xor_sync(0xFFFFFFFFu, z[k], 1);
    }
    den0 += __shfl_xor_sync(0xFFFFFFFFu, den0, 1);
    den1 += __shfl_xor_sync(0xFFFFFFFFu, den1, 1);
    den2 += __shfl_xor_sync(0xFFFFFFFFu, den2, 1);
    den3 += __shfl_xor_sync(0xFFFFFFFFu, den3, 1);
    if (valid) {
        float* yp = d_y + n * 56;
        if (par == 0) {
#pragma unroll
            for (int k = 0; k < 14; k++) { yp[k] = y0[k]; yp[14 + k] = y1[k]; }
            ((float4*)d_den)[n] = make_float4(den0, den1, den2, den3);
        } else {
#pragma unroll
            for (int k = 0; k < 14; k++) { yp[28 + k] = y2[k]; yp[42 + k] = y3[k]; }
        }
        // gc: each pair-thread computes 32 columns
        float dvn = d_xp[n * 16 + 14];
        int c0 = par * 32;
        float4* gout = (float4*)(d_gc + (long)n * 64 + c0);
#pragma unroll
        for (int c4 = 0; c4 < 8; c4++) {
            float a0 = 0.f, a1 = 0.f, a2 = 0.f, a3 = 0.f;
#pragma unroll
            for (int k = 0; k < 14; k++) {
                float zv = z[k];
                const float* wr = &sWg[k][c0 + c4 * 4];
                a0 += zv * wr[0]; a1 += zv * wr[1]; a2 += zv * wr[2]; a3 += zv * wr[3];
            }
            gout[c4] = make_float4(fmaxf(dvn * a0 + sbg[c0 + c4 * 4 + 0], 0.f),
                                   fmaxf(dvn * a1 + sbg[c0 + c4 * 4 + 1], 0.f),
                                   fmaxf(dvn * a2 + sbg[c0 + c4 * 4 + 2], 0.f),
                                   fmaxf(dvn * a3 + sbg[c0 + c4 * 4 + 3], 0.f));
        }
    }
}

// ---------------- fuse2: h2 = elu((y/den)@W1 + b1) @ W2, g1 never materialized ----------------
__global__ void k_fuse2(const float* __restrict__ W1, const float* __restrict__ b1,
                        const float* __restrict__ W2,
                        const float* __restrict__ as2, const float* __restrict__ ad2) {
    __shared__ float sA[64][68];
    __shared__ float sB[64][68];
    __shared__ float sW1c[14][64];
    __shared__ float sYc[64][16];
    __shared__ float sden[64];
    __shared__ float sb1c[64];
    int t = threadIdx.x;
    int nb = blockIdx.x * 64;
    int tn = t >> 4, tc = t & 15;
    float acc[4][4] = {};
#pragma unroll 1
    for (int kc = 0; kc < 4; kc++) {
#pragma unroll
        for (int j = 0; j < 4; j++) {
            int f4 = t * 4 + j;
            int row = f4 >> 4, col4 = f4 & 15;
            float4 wv = ((const float4*)(W2 + (kc * 64 + row) * 64))[col4];
            ((float4*)&sB[row][0])[col4] = wv;
        }
        for (int i = t; i < 14 * 64; i += 256) {
            int k = i >> 6, c = i & 63;
            sW1c[k][c] = W1[k * 256 + kc * 64 + c];
        }
        for (int i = t; i < 64 * 14; i += 256) {
            int row = i / 14, k = i - row * 14;
            int n = nb + row;
            sYc[row][k] = (n < NN) ? d_y[n * 56 + kc * 14 + k] : 0.f;
        }
        if (t < 64) {
            int n = nb + t;
            sden[t] = (n < NN) ? d_den[n * 4 + kc] : 1.f;
            sb1c[t] = b1[kc * 64 + t];
        }
        __syncthreads();
#pragma unroll
        for (int i = 0; i < 4; i++) {
            int row = tn * 4 + i;
            float inv = 1.f / (sden[row] + 1e-16f);
#pragma unroll
            for (int j = 0; j < 4; j++) {
                int col = tc * 4 + j;
                float a2 = 0.f;
#pragma unroll
                for (int k = 0; k < 14; k++) a2 += sYc[row][k] * sW1c[k][col];
                sA[row][col] = elu(a2 * inv + sb1c[col]);
            }
        }
        __syncthreads();
#pragma unroll 4
        for (int kk = 0; kk < 64; kk++) {
            float4 bv = ((float4*)&sB[kk][0])[tc];
#pragma unroll
            for (int i = 0; i < 4; i++) {
                float av = sA[tn * 4 + i][kk];
                acc[i][0] += av * bv.x; acc[i][1] += av * bv.y;
                acc[i][2] += av * bv.z; acc[i][3] += av * bv.w;
            }
        }
        __syncthreads();
    }
    float4 av2 = ((const float4*)as2)[tc];
    float4 dv2 = ((const float4*)ad2)[tc];
#pragma unroll
    for (int i = 0; i < 4; i++) {
        int n = nb + tn * 4 + i;
        float ps = acc[i][0] * av2.x + acc[i][1] * av2.y + acc[i][2] * av2.z + acc[i][3] * av2.w;
        float pd = acc[i][0] * dv2.x + acc[i][1] * dv2.y + acc[i][2] * dv2.z + acc[i][3] * dv2.w;
#pragma unroll
        for (int o = 8; o > 0; o >>= 1) {
            ps += __shfl_down_sync(0xFFFFFFFFu, ps, o, 16);
            pd += __shfl_down_sync(0xFFFFFFFFu, pd, o, 16);
        }
        if (n < NN) {
            ((float4*)(d_h2 + (long)n * 64))[tc] =
                make_float4(acc[i][0], acc[i][1], acc[i][2], acc[i][3]);
            if (tc == 0) { d_ss2[n] = ps; d_sd2[n] = pd; }
        }
    }
}

// ---------------- GAT2 gather + fuse + pool: 4 nodes/warp, Wf staged once ----------------
#define G2W 4
__global__ void k_gat2(const float* __restrict__ b2, const float* __restrict__ bf,
                       const float* __restrict__ Wf,
                       const int* __restrict__ batch) {
    __shared__ float sWf[128 * 64];   // 32KB
    __shared__ float sf[8][128];
    __shared__ float sb2[64], sbf[64];
    int t = threadIdx.x, lane = t & 31, w = t >> 5;
    for (int i = t; i < 128 * 64 / 4; i += 256) ((float4*)sWf)[i] = ((const float4*)Wf)[i];
    if (t < 64) { sb2[t] = b2[t]; sbf[t] = bf[t]; }
    __syncthreads();
#pragma unroll 1
    for (int q = 0; q < G2W; q++) {
        int n = blockIdx.x * (8 * G2W) + w * G2W + q;
        if (n >= NN) continue;
        float sdv = d_sd2[n];
        int beg = d_off[n], end = d_off[n + 1];
        float a0 = 0.f, a1 = 0.f, den = 0.f;
        int i = beg;
        for (; i + 2 <= end; i += 2) {
            int s0 = d_csr[i], s1 = d_csr[i + 1];
            float l0 = d_ss2[s0], l1 = d_ss2[s1];
            float2 h0 = ((const float2*)(d_h2 + (long)s0 * 64))[lane];
            float2 h1v = ((const float2*)(d_h2 + (long)s1 * 64))[lane];
            float e0 = __expf(lrelu(l0 + sdv));
            float e1 = __expf(lrelu(l1 + sdv));
            den += e0 + e1;
            a0 += h0.x * e0 + h1v.x * e1;
            a1 += h0.y * e0 + h1v.y * e1;
        }
        if (i < end) {
            int s = d_csr[i];
            float e = __expf(lrelu(d_ss2[s] + sdv));
            den += e;
            float2 h = ((const float2*)(d_h2 + (long)s * 64))[lane];
            a0 += h.x * e; a1 += h.y * e;
        }
        float inv = 1.f / (den + 1e-16f);
        int c = 2 * lane;
        float2 gcv = ((const float2*)(d_gc + (long)n * 64))[lane];
        sf[w][c]          = elu(a0 * inv + sb2[c]);
        sf[w][c + 1]      = elu(a1 * inv + sb2[c + 1]);
        sf[w][64 + c]     = gcv.x;
        sf[w][64 + c + 1] = gcv.y;
        __syncwarp();
        float acc0 = sbf[c], acc1 = sbf[c + 1];
        const float* sp = sf[w];
#pragma unroll 8
        for (int k = 0; k < 128; k++) {
            float v = sp[k];
            float2 wv = ((const float2*)&sWf[k * 64])[lane];
            acc0 += v * wv.x;
            acc1 += v * wv.y;
        }
        acc0 = fmaxf(acc0, 0.f);
        acc1 = fmaxf(acc1, 0.f);
        int b = batch[n];
        atomicAdd(d_pooled + b * 64 + c, acc0);
        atomicAdd(d_pooled + b * 64 + c + 1, acc1);
        if (lane == 0) atomicAdd(d_gcnt + b, 1.0f);
        __syncwarp();
    }
}

// ---------------- heads: pooled mean -> 2x (relu MLP 64->32->5) ----------------
__global__ void k_head(const float* __restrict__ Wc1, const float* __restrict__ bc1,
                       const float* __restrict__ Wc2, const float* __restrict__ bc2,
                       const float* __restrict__ Wp1, const float* __restrict__ bp1,
                       const float* __restrict__ Wp2, const float* __restrict__ bp2,
                       float* __restrict__ out) {
    int g = blockIdx.x, t = threadIdx.x;
    __shared__ float sp[64], sh[64];
    float cnt = fmaxf(d_gcnt[g], 1.0f);
    sp[t] = d_pooled[g * 64 + t] / cnt;
    __syncthreads();
    float hv;
    if (t < 32) {
        hv = bc1[t];
#pragma unroll 8
        for (int k = 0; k < 64; k++) hv += sp[k] * Wc1[k * 32 + t];
    } else {
        int j = t - 32;
        hv = bp1[j];
#pragma unroll 8
        for (int k = 0; k < 64; k++) hv += sp[k] * Wp1[k * 32 + j];
    }
    sh[t] = fmaxf(hv, 0.f);
    __syncthreads();
    if (t < 5) {
        float o = bc2[t];
#pragma unroll
        for (int j = 0; j < 32; j++) o += sh[j] * Wc2[j * 5 + t];
        out[g * 5 + t] = o;
    } else if (t >= 8 && t < 13) {
        int u = t - 8;
        float o = bp2[u];
#pragma unroll
        for (int j = 0; j < 32; j++) o += sh[32 + j] * Wp2[j * 5 + u];
        out[NG * 5 + g * 5 + u] = o;
    }
}

extern "C" void kernel_launch(void* const* d_in, const int* in_sizes, int n_in,
                              void* d_out, int out_size) {
    const float* x     = (const float*)d_in[0];
    const int*   ei    = (const int*)d_in[1];     // int32 (JAX x64 disabled)
    const int*   batch = (const int*)d_in[3];     // int32
    const float* W1  = (const float*)d_in[4];
    const float* as1 = (const float*)d_in[5];
    const float* ad1 = (const float*)d_in[6];
    const float* b1  = (const float*)d_in[7];
    const float* W2  = (const float*)d_in[8];
    const float* as2 = (const float*)d_in[9];
    const float* ad2 = (const float*)d_in[10];
    const float* b2  = (const float*)d_in[11];
    const float* Wg  = (const float*)d_in[12];
    const float* bg  = (const float*)d_in[13];
    const float* Wf  = (const float*)d_in[14];
    const float* bf  = (const float*)d_in[15];
    const float* Wc1 = (const float*)d_in[16];
    const float* bc1 = (const float*)d_in[17];
    const float* Wc2 = (const float*)d_in[18];
    const float* bc2 = (const float*)d_in[19];
    const float* Wp1 = (const float*)d_in[20];
    const float* bp1 = (const float*)d_in[21];
    const float* Wp2 = (const float*)d_in[22];
    const float* bp2 = (const float*)d_in[23];

    int E  = in_sizes[1] / 2;
    int te = E + NN;
    int eb = (te + 255) / 256;

    k_init<<<512, 256>>>(x, W1, as1, ad1);                    // 0
    k_count<<<eb, 256>>>(ei, E, te);                          // 1
    k_scan1<<<SB, 1024>>>();                                  // 2
    k_scan2<<<1, 64>>>();                                     // 3
    k_scan3<<<(NN + 255) / 256, 256>>>();                     // 4
    k_fill<<<eb, 256>>>(ei, E, te);                           // 5
    k_gather1<<<(2 * NN + 127) / 128, 128>>>(Wg, bg);         // 6
    k_fuse2<<<(NN + 63) / 64, 256>>>(W1, b1, W2, as2, ad2);   // 7
    k_gat2<<<(NN + G2W * 8 - 1) / (G2W * 8), 256>>>(b2, bf, Wf, batch);  // 8
    k_head<<<NG, 64>>>(Wc1, bc1, Wc2, bc2, Wp1, bp1, Wp2, bp2, (float*)d_out); // 9
}